// round 7
// baseline (speedup 1.0000x reference)
#include <cuda_runtime.h>
#include <cuda_fp16.h>
#include <stdint.h>

#define N_NODES    100000
#define N_PAD      100096
#define N_EDGES    300000
#define NUM_GRAPHS 128
#define HIDDEN     256
#define SEM_IN     1536
#define MAX_CHILD  200
#define N_COMBO    (8 * MAX_CHILD)
#define SCAN_B     1024
#define NBLK       ((N_NODES + SCAN_B - 1) / SCAN_B)   // 98

// Scratch (zero-initialized device globals)
__device__ __align__(16) __half g_h[(size_t)N_PAD * HIDDEN];
__device__ __align__(16) __half g_z[(size_t)N_PAD * HIDDEN];
__device__ __align__(16) __half g_w16[SEM_IN * HIDDEN + 4 * HIDDEN * HIDDEN];
__device__ __align__(16) __half g_combo[(size_t)N_COMBO * HIDDEN];
__device__ float  g_pool[NUM_GRAPHS * HIDDEN];
__device__ int    g_deg[N_NODES];
__device__ int    g_off[N_NODES];
__device__ int    g_cur[N_NODES];
__device__ int    g_csr_src[N_EDGES];
__device__ int    g_csr_cid[N_EDGES];
__device__ int    g_bsum[SCAN_B];

#define BM 128
#define BK 32
#define SA_STRIDE 40
#define SB_STRIDE 264
#define ST_STRIDE 264
#define SA_ELEMS (2 * BM * SA_STRIDE)
#define SB_ELEMS (2 * BK * SB_STRIDE)          // fused_mlp (2-stage)
#define SB3_ELEMS (3 * BK * SB_STRIDE)         // embed (3-stage)
#define ST_ELEMS (BM * ST_STRIDE)

// weight region sizes (elements) in g_w16
#define W_SEM_ELEMS (SEM_IN * HIDDEN)
#define W_HH_ELEMS  (HIDDEN * HIDDEN)
#define W_TOTAL     (W_SEM_ELEMS + 4 * W_HH_ELEMS)

// ---------------------------------------------------------------------------
// helpers
// ---------------------------------------------------------------------------
__device__ __forceinline__ void ldsm_x4(uint32_t* r, const __half* p) {
    uint32_t a = (uint32_t)__cvta_generic_to_shared(p);
    asm volatile("ldmatrix.sync.aligned.m8n8.x4.shared.b16 {%0,%1,%2,%3}, [%4];"
                 : "=r"(r[0]), "=r"(r[1]), "=r"(r[2]), "=r"(r[3]) : "r"(a));
}
__device__ __forceinline__ void ldsm_x4t(uint32_t* r, const __half* p) {
    uint32_t a = (uint32_t)__cvta_generic_to_shared(p);
    asm volatile("ldmatrix.sync.aligned.m8n8.x4.trans.shared.b16 {%0,%1,%2,%3}, [%4];"
                 : "=r"(r[0]), "=r"(r[1]), "=r"(r[2]), "=r"(r[3]) : "r"(a));
}
__device__ __forceinline__ void mma16816(float* c, const uint32_t* a,
                                         uint32_t b0, uint32_t b1) {
    asm volatile(
        "mma.sync.aligned.m16n8k16.row.col.f32.f16.f16.f32 "
        "{%0,%1,%2,%3}, {%4,%5,%6,%7}, {%8,%9}, {%0,%1,%2,%3};"
        : "+f"(c[0]), "+f"(c[1]), "+f"(c[2]), "+f"(c[3])
        : "r"(a[0]), "r"(a[1]), "r"(a[2]), "r"(a[3]), "r"(b0), "r"(b1));
}
__device__ __forceinline__ void cp16(void* smem_dst, const void* gsrc) {
    uint32_t s = (uint32_t)__cvta_generic_to_shared(smem_dst);
    asm volatile("cp.async.cg.shared.global [%0], [%1], 16;" :: "r"(s), "l"(gsrc));
}
#define CP_COMMIT() asm volatile("cp.async.commit_group;")
#define CP_WAIT(N)  asm volatile("cp.async.wait_group %0;" :: "n"(N))

// ---------------------------------------------------------------------------
// setup: one kernel converts all weights to fp16 AND zeroes deg.
// ---------------------------------------------------------------------------
#define CVT_TOTAL   (W_TOTAL + N_NODES + 24)
__global__ void cvt_all_kernel(const float* __restrict__ sem_W,
                               const float* __restrict__ W1_0, const float* __restrict__ W2_0,
                               const float* __restrict__ W1_1, const float* __restrict__ W2_1,
                               __half* __restrict__ dst, int* __restrict__ deg)
{
    int e = (blockIdx.x * blockDim.x + threadIdx.x) * 4;
    if (e < W_TOTAL) {
        const float* src;
        int local = e;
        if (local < W_SEM_ELEMS) { src = sem_W; }
        else {
            local -= W_SEM_ELEMS;
            int w = local / W_HH_ELEMS;
            local -= w * W_HH_ELEMS;
            src = (w == 0) ? W1_0 : (w == 1) ? W2_0 : (w == 2) ? W1_1 : W2_1;
        }
        float4 v = *(const float4*)(src + local);
        __half2* d = (__half2*)(dst + e);
        d[0] = __floats2half2_rn(v.x, v.y);
        d[1] = __floats2half2_rn(v.z, v.w);
    } else {
        int i = e - W_TOTAL;
        #pragma unroll
        for (int j = 0; j < 4; j++)
            if (i + j < N_NODES) deg[i + j] = 0;
    }
}

__global__ void combo_kernel(const float* __restrict__ role, const float* __restrict__ child,
                             __half* __restrict__ combo) {
    int rc = blockIdx.x;
    int r = rc / MAX_CHILD, cc = rc % MAX_CHILD;
    int t = threadIdx.x;
    float2 a = *(const float2*)(role + r * HIDDEN + t * 2);
    float2 b = *(const float2*)(child + cc * HIDDEN + t * 2);
    *(__half2*)(combo + (size_t)rc * HIDDEN + t * 2) = __floats2half2_rn(a.x + b.x, a.y + b.y);
}

// ---------------------------------------------------------------------------
// CSR build
// ---------------------------------------------------------------------------
__global__ void count_kernel(const int* __restrict__ eidx, int* __restrict__ deg) {
    int e = blockIdx.x * blockDim.x + threadIdx.x;
    if (e < N_EDGES) atomicAdd(&deg[eidx[N_EDGES + e]], 1);
}
__global__ void __launch_bounds__(SCAN_B) scan1_kernel(
    const int* __restrict__ deg, int* __restrict__ off, int* __restrict__ bsum)
{
    __shared__ int s[SCAN_B];
    int tid = threadIdx.x;
    int i = blockIdx.x * SCAN_B + tid;
    int v = (i < N_NODES) ? deg[i] : 0;
    s[tid] = v; __syncthreads();
    #pragma unroll
    for (int d = 1; d < SCAN_B; d <<= 1) {
        int t = (tid >= d) ? s[tid - d] : 0;
        __syncthreads();
        if (tid >= d) s[tid] += t;
        __syncthreads();
    }
    if (i < N_NODES) off[i] = s[tid] - v;
    if (tid == SCAN_B - 1) bsum[blockIdx.x] = s[tid];
}
__global__ void __launch_bounds__(128) scan2_kernel(int* bsum) {
    __shared__ int s[128];
    int tid = threadIdx.x;
    int v = (tid < NBLK) ? bsum[tid] : 0;
    s[tid] = v; __syncthreads();
    #pragma unroll
    for (int d = 1; d < 128; d <<= 1) {
        int t = (tid >= d) ? s[tid - d] : 0;
        __syncthreads();
        if (tid >= d) s[tid] += t;
        __syncthreads();
    }
    if (tid < NBLK) bsum[tid] = s[tid] - v;
}
__global__ void scan3_kernel(int* __restrict__ off, const int* __restrict__ bsum,
                             int* __restrict__ cur) {
    int i = blockIdx.x * blockDim.x + threadIdx.x;
    if (i < N_NODES) {
        int o = off[i] + bsum[i >> 10];
        off[i] = o;
        cur[i] = o;
    }
}
__global__ void scatter_kernel(const int* __restrict__ eidx, const int* __restrict__ eattr,
                               int* __restrict__ cur,
                               int* __restrict__ csr_src, int* __restrict__ csr_cid) {
    int e = blockIdx.x * blockDim.x + threadIdx.x;
    if (e < N_EDGES) {
        int pos = atomicAdd(&cur[eidx[N_EDGES + e]], 1);
        csr_src[pos] = eidx[e];
        int r  = eattr[2 * e];
        int cc = min(max(eattr[2 * e + 1], 0), MAX_CHILD - 1);
        csr_cid[pos] = r * MAX_CHILD + cc;
    }
}

// ---------------------------------------------------------------------------
// Edge aggregation: HALF-WARP per dst node (2 nodes/warp), unroll-2.
// z[n] = h[n] + sum_e relu(h[src_e] + combo[cid_e])
// Each of 16 lanes handles 2 float4 chunks (32 float4 per 256-col fp16 row).
// ---------------------------------------------------------------------------
__global__ void __launch_bounds__(256) edge_csr_kernel(
    const int*    __restrict__ off,
    const int*    __restrict__ deg,
    const int*    __restrict__ csr_src,
    const int*    __restrict__ csr_cid,
    const __half* __restrict__ combo,
    const __half* __restrict__ h,
    __half*       __restrict__ z)
{
    int wid  = threadIdx.x >> 5;
    int lane = threadIdx.x & 31;
    int half = lane >> 4;            // 0 or 1
    int l16  = lane & 15;
    int n = blockIdx.x * 16 + wid * 2 + half;
    if (n >= N_NODES) return;

    const int c0 = l16;              // float4 chunk indices
    const int c1 = l16 + 16;

    float acc[16];
    {
        const float4* hp4 = (const float4*)(h + (size_t)n * HIDDEN);
        float4 v0 = __ldg(hp4 + c0);
        float4 v1 = __ldg(hp4 + c1);
        __half2* p0 = (__half2*)&v0;
        __half2* p1 = (__half2*)&v1;
        #pragma unroll
        for (int j = 0; j < 4; j++) {
            float2 f0 = __half22float2(p0[j]);
            float2 f1 = __half22float2(p1[j]);
            acc[2 * j + 0] = f0.x;  acc[2 * j + 1] = f0.y;
            acc[8 + 2 * j] = f1.x;  acc[9 + 2 * j] = f1.y;
        }
    }

    int start = off[n];
    int d = deg[n];
    int k = 0;

    auto addEdge4 = [&](float4 sv0, float4 cv0, float4 sv1, float4 cv1) {
        __half2* sp0 = (__half2*)&sv0; __half2* cp0 = (__half2*)&cv0;
        __half2* sp1 = (__half2*)&sv1; __half2* cp1 = (__half2*)&cv1;
        #pragma unroll
        for (int j = 0; j < 4; j++) {
            float2 f0 = __half22float2(sp0[j]);
            float2 g0 = __half22float2(cp0[j]);
            float2 f1 = __half22float2(sp1[j]);
            float2 g1 = __half22float2(cp1[j]);
            acc[2 * j + 0] += fmaxf(f0.x + g0.x, 0.f);
            acc[2 * j + 1] += fmaxf(f0.y + g0.y, 0.f);
            acc[8 + 2 * j] += fmaxf(f1.x + g1.x, 0.f);
            acc[9 + 2 * j] += fmaxf(f1.y + g1.y, 0.f);
        }
    };

    for (; k + 2 <= d; k += 2) {
        int s0 = __ldg(&csr_src[start + k]);
        int i0 = __ldg(&csr_cid[start + k]);
        int s1 = __ldg(&csr_src[start + k + 1]);
        int i1 = __ldg(&csr_cid[start + k + 1]);

        const float4* h0 = (const float4*)(h + (size_t)s0 * HIDDEN);
        const float4* g0 = (const float4*)(combo + (size_t)i0 * HIDDEN);
        const float4* h1 = (const float4*)(h + (size_t)s1 * HIDDEN);
        const float4* g1 = (const float4*)(combo + (size_t)i1 * HIDDEN);

        float4 sa0 = __ldg(h0 + c0), sb0 = __ldg(h0 + c1);
        float4 ca0 = __ldg(g0 + c0), cb0 = __ldg(g0 + c1);
        float4 sa1 = __ldg(h1 + c0), sb1 = __ldg(h1 + c1);
        float4 ca1 = __ldg(g1 + c0), cb1 = __ldg(g1 + c1);

        addEdge4(sa0, ca0, sb0, cb0);
        addEdge4(sa1, ca1, sb1, cb1);
    }
    if (k < d) {
        int s0 = __ldg(&csr_src[start + k]);
        int i0 = __ldg(&csr_cid[start + k]);
        const float4* h0 = (const float4*)(h + (size_t)s0 * HIDDEN);
        const float4* g0 = (const float4*)(combo + (size_t)i0 * HIDDEN);
        float4 sa0 = __ldg(h0 + c0), sb0 = __ldg(h0 + c1);
        float4 ca0 = __ldg(g0 + c0), cb0 = __ldg(g0 + c1);
        addEdge4(sa0, ca0, sb0, cb0);
    }

    float4 o0, o1;
    __half2* q0 = (__half2*)&o0;
    __half2* q1 = (__half2*)&o1;
    #pragma unroll
    for (int j = 0; j < 4; j++) {
        q0[j] = __floats2half2_rn(acc[2 * j + 0], acc[2 * j + 1]);
        q1[j] = __floats2half2_rn(acc[8 + 2 * j], acc[9 + 2 * j]);
    }
    float4* zp4 = (float4*)(z + (size_t)n * HIDDEN);
    zp4[c0] = o0;
    zp4[c1] = o1;
}

// ---------------------------------------------------------------------------
// Embed GEMM (mma.sync): h16 = x_sem(fp32)@sem_W16 + sem_b + label[x0] + type[x1]
// BM=128, BN=256, BK=32, 512 threads; A reg-staged (2-buf); B cp.async 3-buf ring.
// ---------------------------------------------------------------------------
__global__ void __launch_bounds__(512) embed_gemm(
    const float* __restrict__ A, const __half* __restrict__ B,
    const float* __restrict__ bias,
    const int*   __restrict__ xidx,
    const float* __restrict__ label_emb,
    const float* __restrict__ type_emb,
    __half* __restrict__ h_out, int M, int K)
{
    extern __shared__ __half smem[];
    __half* sA = smem;                 // 2 x BM x SA_STRIDE
    __half* sB = smem + SA_ELEMS;      // 3 x BK x SB_STRIDE

    const int tid  = threadIdx.x;
    const int lane = tid & 31;
    const int warp = tid >> 5;
    const int wm   = warp >> 3;
    const int wn   = warp & 7;
    const int mBase = blockIdx.x * BM;

    const int a_row = tid >> 3;
    const int a_col = (tid & 7) << 2;
    const int b_row = tid >> 4;
    const int b_col = (tid & 15) << 3;

    const int KT = K / BK;

    float4 ra[2];
    float acc[4][4][4];
    #pragma unroll
    for (int i = 0; i < 4; i++)
        #pragma unroll
        for (int j = 0; j < 4; j++)
            #pragma unroll
            for (int q = 0; q < 4; q++) acc[i][j][q] = 0.f;

    auto ldgA = [&](int kt) {
        #pragma unroll
        for (int i = 0; i < 2; i++) {
            int r = mBase + a_row + i * 64;
            if (r < M) ra[i] = *(const float4*)(A + (size_t)r * K + kt * BK + a_col);
            else       ra[i] = make_float4(0.f, 0.f, 0.f, 0.f);
        }
    };
    auto stsA = [&](int st) {
        #pragma unroll
        for (int i = 0; i < 2; i++) {
            __half2* p = (__half2*)&sA[st * BM * SA_STRIDE + (a_row + i * 64) * SA_STRIDE + a_col];
            p[0] = __floats2half2_rn(ra[i].x, ra[i].y);
            p[1] = __floats2half2_rn(ra[i].z, ra[i].w);
        }
    };
    auto cpB = [&](int kt, int buf) {
        const __half* g = B + (size_t)(kt * BK + b_row) * HIDDEN + b_col;
        __half* s = &sB[buf * BK * SB_STRIDE + b_row * SB_STRIDE + b_col];
        cp16(s, g);
        cp16(s + 128, g + 128);
    };

    // prologue: B two tiles ahead, A one tile staged
    cpB(0, 0); CP_COMMIT();
    cpB(1, 1); CP_COMMIT();
    ldgA(0); stsA(0);
    CP_WAIT(1); __syncthreads();

    for (int kt = 0; kt < KT; kt++) {
        const int sa = kt & 1;
        const int sb = kt % 3;
        if (kt + 2 < KT) { cpB(kt + 2, (kt + 2) % 3); CP_COMMIT(); }
        if (kt + 1 < KT) ldgA(kt + 1);
        #pragma unroll
        for (int ks = 0; ks < 2; ks++) {
            uint32_t af[4][4], bf[2][4];
            #pragma unroll
            for (int mi = 0; mi < 4; mi++)
                ldsm_x4(af[mi], &sA[sa * BM * SA_STRIDE
                         + (wm * 64 + mi * 16 + (lane & 15)) * SA_STRIDE
                         + ks * 16 + (lane >> 4) * 8]);
            #pragma unroll
            for (int p2 = 0; p2 < 2; p2++) {
                int krow = ks * 16 + (lane & 7) + ((lane >> 3) & 1) * 8;
                int ncol = wn * 32 + p2 * 16 + (lane >> 4) * 8;
                ldsm_x4t(bf[p2], &sB[sb * BK * SB_STRIDE + krow * SB_STRIDE + ncol]);
            }
            #pragma unroll
            for (int mi = 0; mi < 4; mi++)
                #pragma unroll
                for (int ni = 0; ni < 4; ni++)
                    mma16816(acc[mi][ni], af[mi],
                             bf[ni >> 1][(ni & 1) * 2 + 0], bf[ni >> 1][(ni & 1) * 2 + 1]);
        }
        if (kt + 1 < KT) stsA(sa ^ 1);
        if (kt + 2 < KT) { CP_WAIT(1); } else { CP_WAIT(0); }
        __syncthreads();
    }

    #pragma unroll
    for (int mi = 0; mi < 4; mi++) {
        int r0 = mBase + wm * 64 + mi * 16 + (lane >> 2);
        #pragma unroll
        for (int hh = 0; hh < 2; hh++) {
            int r = r0 + hh * 8;
            if (r >= M) continue;
            int x0 = xidx[2 * r], x1 = xidx[2 * r + 1];
            #pragma unroll
            for (int ni = 0; ni < 4; ni++) {
                int c = wn * 32 + ni * 8 + (lane & 3) * 2;
                float v0 = acc[mi][ni][hh * 2 + 0] + bias[c]
                         + label_emb[(size_t)x0 * HIDDEN + c] + type_emb[x1 * HIDDEN + c];
                float v1 = acc[mi][ni][hh * 2 + 1] + bias[c + 1]
                         + label_emb[(size_t)x0 * HIDDEN + c + 1] + type_emb[x1 * HIDDEN + c + 1];
                *(__half2*)(h_out + (size_t)r * HIDDEN + c) = __floats2half2_rn(v0, v1);
            }
        }
    }
}

// ---------------------------------------------------------------------------
// Fused MLP: h16 = relu(z16 @ W1_16 + b1) @ W2_16 + b2 (t staged in smem)
// ---------------------------------------------------------------------------
__global__ void __launch_bounds__(512) fused_mlp(
    const __half* __restrict__ Z,
    const __half* __restrict__ W1, const float* __restrict__ b1,
    const __half* __restrict__ W2, const float* __restrict__ b2,
    __half* __restrict__ h_out, int M)
{
    extern __shared__ __half hsm[];
    __half* sT = hsm;
    __half* sA = hsm + ST_ELEMS;
    __half* sB = hsm + ST_ELEMS + SA_ELEMS;

    const int tid  = threadIdx.x;
    const int lane = tid & 31;
    const int warp = tid >> 5;
    const int wm   = warp >> 3;
    const int wn   = warp & 7;
    const int mBase = blockIdx.x * BM;

    const int a_row = tid >> 2;
    const int a_col = (tid & 3) << 3;
    const int b_row = tid >> 4;
    const int b_col = (tid & 15) << 3;

    const int KT = HIDDEN / BK;

    float acc[4][4][4];
    #pragma unroll
    for (int i = 0; i < 4; i++)
        #pragma unroll
        for (int j = 0; j < 4; j++)
            #pragma unroll
            for (int q = 0; q < 4; q++) acc[i][j][q] = 0.f;

    auto cpA = [&](int kt, int st) {
        cp16(&sA[st * BM * SA_STRIDE + a_row * SA_STRIDE + a_col],
             Z + (size_t)(mBase + a_row) * HIDDEN + kt * BK + a_col);
    };
    auto cpB = [&](const __half* W, int kt, int st) {
        const __half* g = W + (size_t)(kt * BK + b_row) * HIDDEN + b_col;
        __half* s = &sB[st * BK * SB_STRIDE + b_row * SB_STRIDE + b_col];
        cp16(s, g);
        cp16(s + 128, g + 128);
    };
    auto compute = [&](const __half* aBase, int aStride, int aColOff, int st) {
        #pragma unroll
        for (int ks = 0; ks < 2; ks++) {
            uint32_t af[4][4], bf[2][4];
            #pragma unroll
            for (int mi = 0; mi < 4; mi++)
                ldsm_x4(af[mi], aBase
                         + (wm * 64 + mi * 16 + (lane & 15)) * aStride
                         + aColOff + ks * 16 + (lane >> 4) * 8);
            #pragma unroll
            for (int p2 = 0; p2 < 2; p2++) {
                int krow = ks * 16 + (lane & 7) + ((lane >> 3) & 1) * 8;
                int ncol = wn * 32 + p2 * 16 + (lane >> 4) * 8;
                ldsm_x4t(bf[p2], &sB[st * BK * SB_STRIDE + krow * SB_STRIDE + ncol]);
            }
            #pragma unroll
            for (int mi = 0; mi < 4; mi++)
                #pragma unroll
                for (int ni = 0; ni < 4; ni++)
                    mma16816(acc[mi][ni], af[mi],
                             bf[ni >> 1][(ni & 1) * 2 + 0], bf[ni >> 1][(ni & 1) * 2 + 1]);
        }
    };

    cpA(0, 0); cpB(W1, 0, 0); CP_COMMIT(); CP_WAIT(0); __syncthreads();
    for (int kt = 0; kt < KT; kt++) {
        const int st = kt & 1;
        if (kt + 1 < KT) { cpA(kt + 1, st ^ 1); cpB(W1, kt + 1, st ^ 1); CP_COMMIT(); }
        compute(&sA[st * BM * SA_STRIDE], SA_STRIDE, 0, st);
        if (kt + 1 < KT) CP_WAIT(0);
        __syncthreads();
    }

    #pragma unroll
    for (int mi = 0; mi < 4; mi++) {
        int rl = wm * 64 + mi * 16 + (lane >> 2);
        #pragma unroll
        for (int hh = 0; hh < 2; hh++) {
            int rr = rl + hh * 8;
            #pragma unroll
            for (int ni = 0; ni < 4; ni++) {
                int c = wn * 32 + ni * 8 + (lane & 3) * 2;
                float v0 = fmaxf(acc[mi][ni][hh * 2 + 0] + b1[c], 0.f);
                float v1 = fmaxf(acc[mi][ni][hh * 2 + 1] + b1[c + 1], 0.f);
                *(__half2*)&sT[rr * ST_STRIDE + c] = __floats2half2_rn(v0, v1);
                acc[mi][ni][hh * 2 + 0] = 0.f;
                acc[mi][ni][hh * 2 + 1] = 0.f;
            }
        }
    }

    cpB(W2, 0, 0); CP_COMMIT(); CP_WAIT(0); __syncthreads();
    for (int kt = 0; kt < KT; kt++) {
        const int st = kt & 1;
        if (kt + 1 < KT) { cpB(W2, kt + 1, st ^ 1); CP_COMMIT(); }
        compute(sT, ST_STRIDE, kt * BK, st);
        if (kt + 1 < KT) CP_WAIT(0);
        __syncthreads();
    }

    #pragma unroll
    for (int mi = 0; mi < 4; mi++) {
        int r0 = mBase + wm * 64 + mi * 16 + (lane >> 2);
        #pragma unroll
        for (int hh = 0; hh < 2; hh++) {
            int r = r0 + hh * 8;
            if (r >= M) continue;
            #pragma unroll
            for (int ni = 0; ni < 4; ni++) {
                int c = wn * 32 + ni * 8 + (lane & 3) * 2;
                float v0 = acc[mi][ni][hh * 2 + 0] + b2[c];
                float v1 = acc[mi][ni][hh * 2 + 1] + b2[c + 1];
                *(__half2*)(h_out + (size_t)r * HIDDEN + c) = __floats2half2_rn(v0, v1);
            }
        }
    }
}

// ---------------------------------------------------------------------------
// Pool (4-way row-parallel) + projection
// ---------------------------------------------------------------------------
__global__ void __launch_bounds__(512) pool_kernel(
    const __half* __restrict__ h,
    const int*    __restrict__ batch,
    float*        __restrict__ pooled)
{
    __shared__ float2 sbuf[4][128];
    int g = blockIdx.x;
    int tid = threadIdx.x;
    int rs = tid >> 7, c2 = tid & 127;

    int lo = 0, hi = N_NODES;
    while (lo < hi) { int mid = (lo + hi) >> 1; if (batch[mid] < g) lo = mid + 1; else hi = mid; }
    int start = lo;
    hi = N_NODES;
    while (lo < hi) { int mid = (lo + hi) >> 1; if (batch[mid] < g + 1) lo = mid + 1; else hi = mid; }
    int end = lo;

    float2 acc = make_float2(0.f, 0.f);
    for (int r = start + rs; r < end; r += 4) {
        float2 f = __half22float2(__ldg((const __half2*)(h + (size_t)r * HIDDEN) + c2));
        acc.x += f.x; acc.y += f.y;
    }
    sbuf[rs][c2] = acc;
    __syncthreads();
    if (rs == 0) {
        float2 s = sbuf[0][c2];
        #pragma unroll
        for (int j = 1; j < 4; j++) { s.x += sbuf[j][c2].x; s.y += sbuf[j][c2].y; }
        float inv = 1.f / fmaxf((float)(end - start), 1.f);
        *(float2*)(pooled + g * HIDDEN + c2 * 2) = make_float2(s.x * inv, s.y * inv);
    }
}

__global__ void __launch_bounds__(HIDDEN) proj_kernel(
    const float* __restrict__ pooled,
    const float* __restrict__ W,
    const float* __restrict__ b,
    float*       __restrict__ out)
{
    int g = blockIdx.x;
    int t = threadIdx.x;
    float acc = b[t];
    #pragma unroll 8
    for (int k = 0; k < HIDDEN; k++)
        acc += pooled[g * HIDDEN + k] * W[k * HIDDEN + t];
    out[g * HIDDEN + t] = acc;
}

// ---------------------------------------------------------------------------
extern "C" void kernel_launch(void* const* d_in, const int* in_sizes, int n_in,
                              void* d_out, int out_size)
{
    const int*   x        = (const int*)  d_in[0];
    const float* x_sem    = (const float*)d_in[1];
    const int*   eattr    = (const int*)  d_in[2];
    const int*   eidx     = (const int*)  d_in[3];
    const int*   batch    = (const int*)  d_in[4];
    const float* label    = (const float*)d_in[5];
    const float* type_emb = (const float*)d_in[6];
    const float* sem_W    = (const float*)d_in[7];
    const float* sem_b    = (const float*)d_in[8];
    const float* role     = (const float*)d_in[9];
    const float* child    = (const float*)d_in[10];
    const float* W1_0     = (const float*)d_in[11];
    const float* b1_0     = (const float*)d_in[12];
    const float* W2_0     = (const float*)d_in[13];
    const float* b2_0     = (const float*)d_in[14];
    const float* W1_1     = (const float*)d_in[15];
    const float* b1_1     = (const float*)d_in[16];
    const float* W2_1     = (const float*)d_in[17];
    const float* b2_1     = (const float*)d_in[18];
    const float* proj_W   = (const float*)d_in[19];
    const float* proj_b   = (const float*)d_in[20];
    float* out = (float*)d_out;

    __half *hP, *zP, *wP, *comboP;
    float *pP;
    int *degP, *offP, *curP, *srcP, *cidP, *bsP;
    cudaGetSymbolAddress((void**)&hP, g_h);
    cudaGetSymbolAddress((void**)&zP, g_z);
    cudaGetSymbolAddress((void**)&wP, g_w16);
    cudaGetSymbolAddress((void**)&comboP, g_combo);
    cudaGetSymbolAddress((void**)&pP, g_pool);
    cudaGetSymbolAddress((void**)&degP, g_deg);
    cudaGetSymbolAddress((void**)&offP, g_off);
    cudaGetSymbolAddress((void**)&curP, g_cur);
    cudaGetSymbolAddress((void**)&srcP, g_csr_src);
    cudaGetSymbolAddress((void**)&cidP, g_csr_cid);
    cudaGetSymbolAddress((void**)&bsP, g_bsum);

    __half* w_sem = wP;
    __half* w1_0  = wP + W_SEM_ELEMS;
    __half* w2_0  = w1_0 + W_HH_ELEMS;
    __half* w1_1  = w2_0 + W_HH_ELEMS;
    __half* w2_1  = w1_1 + W_HH_ELEMS;

    const int embed_smem = (SA_ELEMS + SB3_ELEMS) * (int)sizeof(__half);
    const int fused_smem = (ST_ELEMS + SA_ELEMS + SB_ELEMS) * (int)sizeof(__half);
    cudaFuncSetAttribute(embed_gemm, cudaFuncAttributeMaxDynamicSharedMemorySize, embed_smem);
    cudaFuncSetAttribute(fused_mlp,  cudaFuncAttributeMaxDynamicSharedMemorySize, fused_smem);

    const int gemm_blocks = (N_NODES + BM - 1) / BM;      // 782
    const int node_blocks = (N_NODES + 15) / 16;          // 6250 (2 nodes/warp)

    // Launch order: embed_gemm is MY 4th launch -> it's the profiled one.
    cvt_all_kernel<<<(CVT_TOTAL / 4 + 255) / 256, 256>>>(
        sem_W, W1_0, W2_0, W1_1, W2_1, wP, degP);                       // 1
    combo_kernel<<<N_COMBO, 128>>>(role, child, comboP);                // 2
    count_kernel<<<(N_EDGES + 255) / 256, 256>>>(eidx, degP);           // 3
    embed_gemm<<<gemm_blocks, 512, embed_smem>>>(                       // 4 (PROFILED)
        x_sem, w_sem, sem_b, x, label, type_emb, hP, N_NODES, SEM_IN);

    // CSR (independent of embed result)
    scan1_kernel<<<NBLK, SCAN_B>>>(degP, offP, bsP);
    scan2_kernel<<<1, 128>>>(bsP);
    scan3_kernel<<<(N_NODES + 255) / 256, 256>>>(offP, bsP, curP);
    scatter_kernel<<<(N_EDGES + 255) / 256, 256>>>(eidx, eattr, curP, srcP, cidP);

    // GINE layer 0
    edge_csr_kernel<<<node_blocks, 256>>>(offP, degP, srcP, cidP, comboP, hP, zP);
    fused_mlp<<<gemm_blocks, 512, fused_smem>>>(zP, w1_0, b1_0, w2_0, b2_0, hP, N_NODES);

    // GINE layer 1
    edge_csr_kernel<<<node_blocks, 256>>>(offP, degP, srcP, cidP, comboP, hP, zP);
    fused_mlp<<<gemm_blocks, 512, fused_smem>>>(zP, w1_1, b1_1, w2_1, b2_1, hP, N_NODES);

    // pool + projection
    pool_kernel<<<NUM_GRAPHS, 512>>>(hP, batch, pP);
    proj_kernel<<<NUM_GRAPHS, HIDDEN>>>(pP, proj_W, proj_b, out);
}

// round 8
// speedup vs baseline: 1.0910x; 1.0910x over previous
#include <cuda_runtime.h>
#include <cuda_fp16.h>
#include <stdint.h>

#define N_NODES    100000
#define N_PAD      100096
#define N_EDGES    300000
#define NUM_GRAPHS 128
#define HIDDEN     256
#define SEM_IN     1536
#define MAX_CHILD  200
#define N_COMBO    (8 * MAX_CHILD)
#define SCAN_B     1024
#define NBLK       ((N_NODES + SCAN_B - 1) / SCAN_B)   // 98

// Scratch (zero-initialized device globals)
__device__ __align__(16) __half g_h[(size_t)N_PAD * HIDDEN];
__device__ __align__(16) __half g_z[(size_t)N_PAD * HIDDEN];
__device__ __align__(16) __half g_w16[SEM_IN * HIDDEN + 4 * HIDDEN * HIDDEN];
__device__ __align__(16) __half g_combo[(size_t)N_COMBO * HIDDEN];
__device__ float  g_pool[NUM_GRAPHS * HIDDEN];
__device__ int    g_deg[N_NODES];
__device__ int    g_off[N_NODES];
__device__ int    g_cur[N_NODES];
__device__ int    g_csr_src[N_EDGES];
__device__ int    g_csr_cid[N_EDGES];
__device__ int    g_bsum[SCAN_B];

// fused_mlp tiling (unchanged, known-good)
#define BM 128
#define BK 32
#define SA_STRIDE 40
#define SB_STRIDE 264
#define ST_STRIDE 264
#define SA_ELEMS (2 * BM * SA_STRIDE)
#define SB_ELEMS (2 * BK * SB_STRIDE)
#define ST_ELEMS (BM * ST_STRIDE)

// embed tiling: BM=64, BN=256, 256 threads, 2 CTAs/SM
#define EBM 64
#define ESA_ELEMS (2 * EBM * SA_STRIDE)
#define ESB_ELEMS (2 * BK * SB_STRIDE)

// weight region sizes (elements) in g_w16
#define W_SEM_ELEMS (SEM_IN * HIDDEN)
#define W_HH_ELEMS  (HIDDEN * HIDDEN)
#define W_TOTAL     (W_SEM_ELEMS + 4 * W_HH_ELEMS)

// ---------------------------------------------------------------------------
// helpers
// ---------------------------------------------------------------------------
__device__ __forceinline__ void ldsm_x4(uint32_t* r, const __half* p) {
    uint32_t a = (uint32_t)__cvta_generic_to_shared(p);
    asm volatile("ldmatrix.sync.aligned.m8n8.x4.shared.b16 {%0,%1,%2,%3}, [%4];"
                 : "=r"(r[0]), "=r"(r[1]), "=r"(r[2]), "=r"(r[3]) : "r"(a));
}
__device__ __forceinline__ void ldsm_x4t(uint32_t* r, const __half* p) {
    uint32_t a = (uint32_t)__cvta_generic_to_shared(p);
    asm volatile("ldmatrix.sync.aligned.m8n8.x4.trans.shared.b16 {%0,%1,%2,%3}, [%4];"
                 : "=r"(r[0]), "=r"(r[1]), "=r"(r[2]), "=r"(r[3]) : "r"(a));
}
__device__ __forceinline__ void mma16816(float* c, const uint32_t* a,
                                         uint32_t b0, uint32_t b1) {
    asm volatile(
        "mma.sync.aligned.m16n8k16.row.col.f32.f16.f16.f32 "
        "{%0,%1,%2,%3}, {%4,%5,%6,%7}, {%8,%9}, {%0,%1,%2,%3};"
        : "+f"(c[0]), "+f"(c[1]), "+f"(c[2]), "+f"(c[3])
        : "r"(a[0]), "r"(a[1]), "r"(a[2]), "r"(a[3]), "r"(b0), "r"(b1));
}
__device__ __forceinline__ void cp16(void* smem_dst, const void* gsrc) {
    uint32_t s = (uint32_t)__cvta_generic_to_shared(smem_dst);
    asm volatile("cp.async.cg.shared.global [%0], [%1], 16;" :: "r"(s), "l"(gsrc));
}
#define CP_COMMIT() asm volatile("cp.async.commit_group;")
#define CP_WAIT(N)  asm volatile("cp.async.wait_group %0;" :: "n"(N))

// ---------------------------------------------------------------------------
// setup: one kernel converts all weights to fp16 AND zeroes deg.
// ---------------------------------------------------------------------------
#define CVT_TOTAL   (W_TOTAL + N_NODES + 24)
__global__ void cvt_all_kernel(const float* __restrict__ sem_W,
                               const float* __restrict__ W1_0, const float* __restrict__ W2_0,
                               const float* __restrict__ W1_1, const float* __restrict__ W2_1,
                               __half* __restrict__ dst, int* __restrict__ deg)
{
    int e = (blockIdx.x * blockDim.x + threadIdx.x) * 4;
    if (e < W_TOTAL) {
        const float* src;
        int local = e;
        if (local < W_SEM_ELEMS) { src = sem_W; }
        else {
            local -= W_SEM_ELEMS;
            int w = local / W_HH_ELEMS;
            local -= w * W_HH_ELEMS;
            src = (w == 0) ? W1_0 : (w == 1) ? W2_0 : (w == 2) ? W1_1 : W2_1;
        }
        float4 v = *(const float4*)(src + local);
        __half2* d = (__half2*)(dst + e);
        d[0] = __floats2half2_rn(v.x, v.y);
        d[1] = __floats2half2_rn(v.z, v.w);
    } else {
        int i = e - W_TOTAL;
        #pragma unroll
        for (int j = 0; j < 4; j++)
            if (i + j < N_NODES) deg[i + j] = 0;
    }
}

__global__ void combo_kernel(const float* __restrict__ role, const float* __restrict__ child,
                             __half* __restrict__ combo) {
    int rc = blockIdx.x;
    int r = rc / MAX_CHILD, cc = rc % MAX_CHILD;
    int t = threadIdx.x;
    float2 a = *(const float2*)(role + r * HIDDEN + t * 2);
    float2 b = *(const float2*)(child + cc * HIDDEN + t * 2);
    *(__half2*)(combo + (size_t)rc * HIDDEN + t * 2) = __floats2half2_rn(a.x + b.x, a.y + b.y);
}

// ---------------------------------------------------------------------------
// CSR build
// ---------------------------------------------------------------------------
__global__ void count_kernel(const int* __restrict__ eidx, int* __restrict__ deg) {
    int e = blockIdx.x * blockDim.x + threadIdx.x;
    if (e < N_EDGES) atomicAdd(&deg[eidx[N_EDGES + e]], 1);
}
__global__ void __launch_bounds__(SCAN_B) scan1_kernel(
    const int* __restrict__ deg, int* __restrict__ off, int* __restrict__ bsum)
{
    __shared__ int s[SCAN_B];
    int tid = threadIdx.x;
    int i = blockIdx.x * SCAN_B + tid;
    int v = (i < N_NODES) ? deg[i] : 0;
    s[tid] = v; __syncthreads();
    #pragma unroll
    for (int d = 1; d < SCAN_B; d <<= 1) {
        int t = (tid >= d) ? s[tid - d] : 0;
        __syncthreads();
        if (tid >= d) s[tid] += t;
        __syncthreads();
    }
    if (i < N_NODES) off[i] = s[tid] - v;
    if (tid == SCAN_B - 1) bsum[blockIdx.x] = s[tid];
}
__global__ void __launch_bounds__(128) scan2_kernel(int* bsum) {
    __shared__ int s[128];
    int tid = threadIdx.x;
    int v = (tid < NBLK) ? bsum[tid] : 0;
    s[tid] = v; __syncthreads();
    #pragma unroll
    for (int d = 1; d < 128; d <<= 1) {
        int t = (tid >= d) ? s[tid - d] : 0;
        __syncthreads();
        if (tid >= d) s[tid] += t;
        __syncthreads();
    }
    if (tid < NBLK) bsum[tid] = s[tid] - v;
}
__global__ void scan3_kernel(int* __restrict__ off, const int* __restrict__ bsum,
                             int* __restrict__ cur) {
    int i = blockIdx.x * blockDim.x + threadIdx.x;
    if (i < N_NODES) {
        int o = off[i] + bsum[i >> 10];
        off[i] = o;
        cur[i] = o;
    }
}
__global__ void scatter_kernel(const int* __restrict__ eidx, const int* __restrict__ eattr,
                               int* __restrict__ cur,
                               int* __restrict__ csr_src, int* __restrict__ csr_cid) {
    int e = blockIdx.x * blockDim.x + threadIdx.x;
    if (e < N_EDGES) {
        int pos = atomicAdd(&cur[eidx[N_EDGES + e]], 1);
        csr_src[pos] = eidx[e];
        int r  = eattr[2 * e];
        int cc = min(max(eattr[2 * e + 1], 0), MAX_CHILD - 1);
        csr_cid[pos] = r * MAX_CHILD + cc;
    }
}

// ---------------------------------------------------------------------------
// Edge aggregation (round-6 measured-good form): one warp per dst node, unroll-2.
// z[n] = h[n] + sum_e relu(h[src_e] + combo[cid_e])
// ---------------------------------------------------------------------------
__global__ void __launch_bounds__(256) edge_csr_kernel(
    const int*    __restrict__ off,
    const int*    __restrict__ deg,
    const int*    __restrict__ csr_src,
    const int*    __restrict__ csr_cid,
    const __half* __restrict__ combo,
    const __half* __restrict__ h,
    __half*       __restrict__ z)
{
    int n = blockIdx.x * 8 + (threadIdx.x >> 5);
    if (n >= N_NODES) return;
    int lane = threadIdx.x & 31;

    float4 hv = __ldg((const float4*)(h + (size_t)n * HIDDEN) + lane);
    __half2* hp = (__half2*)&hv;
    float2 a0 = __half22float2(hp[0]), a1 = __half22float2(hp[1]);
    float2 a2 = __half22float2(hp[2]), a3 = __half22float2(hp[3]);
    float acc[8] = {a0.x, a0.y, a1.x, a1.y, a2.x, a2.y, a3.x, a3.y};

    int start = off[n];
    int d = deg[n];
    int k = 0;

    for (; k + 2 <= d; k += 2) {
        int s0 = __ldg(&csr_src[start + k]);
        int c0 = __ldg(&csr_cid[start + k]);
        int s1 = __ldg(&csr_src[start + k + 1]);
        int c1 = __ldg(&csr_cid[start + k + 1]);

        float4 sv0 = __ldg((const float4*)(h + (size_t)s0 * HIDDEN) + lane);
        float4 cv0 = __ldg((const float4*)(combo + (size_t)c0 * HIDDEN) + lane);
        float4 sv1 = __ldg((const float4*)(h + (size_t)s1 * HIDDEN) + lane);
        float4 cv1 = __ldg((const float4*)(combo + (size_t)c1 * HIDDEN) + lane);

        __half2* sp0 = (__half2*)&sv0; __half2* cp0 = (__half2*)&cv0;
        __half2* sp1 = (__half2*)&sv1; __half2* cp1 = (__half2*)&cv1;
        #pragma unroll
        for (int j = 0; j < 4; j++) {
            float2 f0 = __half22float2(sp0[j]);
            float2 g0 = __half22float2(cp0[j]);
            float2 f1 = __half22float2(sp1[j]);
            float2 g1 = __half22float2(cp1[j]);
            acc[2 * j + 0] += fmaxf(f0.x + g0.x, 0.f) + fmaxf(f1.x + g1.x, 0.f);
            acc[2 * j + 1] += fmaxf(f0.y + g0.y, 0.f) + fmaxf(f1.y + g1.y, 0.f);
        }
    }
    if (k < d) {
        int s0 = __ldg(&csr_src[start + k]);
        int c0 = __ldg(&csr_cid[start + k]);
        float4 sv0 = __ldg((const float4*)(h + (size_t)s0 * HIDDEN) + lane);
        float4 cv0 = __ldg((const float4*)(combo + (size_t)c0 * HIDDEN) + lane);
        __half2* sp0 = (__half2*)&sv0; __half2* cp0 = (__half2*)&cv0;
        #pragma unroll
        for (int j = 0; j < 4; j++) {
            float2 f0 = __half22float2(sp0[j]);
            float2 g0 = __half22float2(cp0[j]);
            acc[2 * j + 0] += fmaxf(f0.x + g0.x, 0.f);
            acc[2 * j + 1] += fmaxf(f0.y + g0.y, 0.f);
        }
    }

    float4 outv;
    __half2* op = (__half2*)&outv;
    op[0] = __floats2half2_rn(acc[0], acc[1]);
    op[1] = __floats2half2_rn(acc[2], acc[3]);
    op[2] = __floats2half2_rn(acc[4], acc[5]);
    op[3] = __floats2half2_rn(acc[6], acc[7]);
    ((float4*)(z + (size_t)n * HIDDEN))[lane] = outv;
}

// ---------------------------------------------------------------------------
// Embed GEMM: BM=64, BN=256, BK=32, 256 threads, 2 CTAs/SM.
// 8 warps as 2x4, warp tile 32x64, acc[2][8][4]=64 regs.
// h16 = x_sem(fp32)@sem_W16 + sem_b + label[x0] + type[x1]
// ---------------------------------------------------------------------------
__global__ void __launch_bounds__(256, 2) embed_gemm(
    const float* __restrict__ A, const __half* __restrict__ B,
    const float* __restrict__ bias,
    const int*   __restrict__ xidx,
    const float* __restrict__ label_emb,
    const float* __restrict__ type_emb,
    __half* __restrict__ h_out, int M, int K)
{
    extern __shared__ __half smem[];
    __half* sA = smem;                 // 2 x EBM x SA_STRIDE
    __half* sB = smem + ESA_ELEMS;     // 2 x BK x SB_STRIDE

    const int tid  = threadIdx.x;
    const int lane = tid & 31;
    const int warp = tid >> 5;
    const int wm   = warp >> 2;        // 0..1 -> 32-row span
    const int wn   = warp & 3;         // 0..3 -> 64-col span
    const int mBase = blockIdx.x * EBM;

    const int a_row = tid >> 3;        // 0..31 (+32)
    const int a_col = (tid & 7) << 2;  // float col 0..28

    const int KT = K / BK;

    float4 ra[2];
    float acc[2][8][4];
    #pragma unroll
    for (int i = 0; i < 2; i++)
        #pragma unroll
        for (int j = 0; j < 8; j++)
            #pragma unroll
            for (int q = 0; q < 4; q++) acc[i][j][q] = 0.f;

    auto ldgA = [&](int kt) {
        #pragma unroll
        for (int i = 0; i < 2; i++) {
            int r = mBase + a_row + i * 32;
            if (r < M) ra[i] = *(const float4*)(A + (size_t)r * K + kt * BK + a_col);
            else       ra[i] = make_float4(0.f, 0.f, 0.f, 0.f);
        }
    };
    auto stsA = [&](int st) {
        #pragma unroll
        for (int i = 0; i < 2; i++) {
            __half2* p = (__half2*)&sA[st * EBM * SA_STRIDE + (a_row + i * 32) * SA_STRIDE + a_col];
            p[0] = __floats2half2_rn(ra[i].x, ra[i].y);
            p[1] = __floats2half2_rn(ra[i].z, ra[i].w);
        }
    };
    auto cpB = [&](int kt, int st) {
        // B tile: 32 rows x 256 halves = 1024 x 16B chunks; 256 thr x 4
        #pragma unroll
        for (int i = 0; i < 4; i++) {
            int idx = tid + i * 256;
            int row = idx >> 5;            // 0..31
            int ch  = idx & 31;            // 16B chunk 0..31
            cp16(&sB[st * BK * SB_STRIDE + row * SB_STRIDE + ch * 8],
                 B + (size_t)(kt * BK + row) * HIDDEN + ch * 8);
        }
    };

    ldgA(0); cpB(0, 0); CP_COMMIT();
    stsA(0); CP_WAIT(0); __syncthreads();

    for (int kt = 0; kt < KT; kt++) {
        const int st = kt & 1;
        if (kt + 1 < KT) { ldgA(kt + 1); cpB(kt + 1, st ^ 1); CP_COMMIT(); }
        #pragma unroll
        for (int ks = 0; ks < 2; ks++) {
            uint32_t af[2][4], bf[4][4];
            #pragma unroll
            for (int mi = 0; mi < 2; mi++)
                ldsm_x4(af[mi], &sA[st * EBM * SA_STRIDE
                         + (wm * 32 + mi * 16 + (lane & 15)) * SA_STRIDE
                         + ks * 16 + (lane >> 4) * 8]);
            #pragma unroll
            for (int p2 = 0; p2 < 4; p2++) {
                int krow = ks * 16 + (lane & 7) + ((lane >> 3) & 1) * 8;
                int ncol = wn * 64 + p2 * 16 + (lane >> 4) * 8;
                ldsm_x4t(bf[p2], &sB[st * BK * SB_STRIDE + krow * SB_STRIDE + ncol]);
            }
            #pragma unroll
            for (int mi = 0; mi < 2; mi++)
                #pragma unroll
                for (int ni = 0; ni < 8; ni++)
                    mma16816(acc[mi][ni], af[mi],
                             bf[ni >> 1][(ni & 1) * 2 + 0], bf[ni >> 1][(ni & 1) * 2 + 1]);
        }
        if (kt + 1 < KT) { stsA(st ^ 1); CP_WAIT(0); }
        __syncthreads();
    }

    #pragma unroll
    for (int mi = 0; mi < 2; mi++) {
        int r0 = mBase + wm * 32 + mi * 16 + (lane >> 2);
        #pragma unroll
        for (int hh = 0; hh < 2; hh++) {
            int r = r0 + hh * 8;
            if (r >= M) continue;
            int x0 = xidx[2 * r], x1 = xidx[2 * r + 1];
            #pragma unroll
            for (int ni = 0; ni < 8; ni++) {
                int c = wn * 64 + ni * 8 + (lane & 3) * 2;
                float v0 = acc[mi][ni][hh * 2 + 0] + bias[c]
                         + label_emb[(size_t)x0 * HIDDEN + c] + type_emb[x1 * HIDDEN + c];
                float v1 = acc[mi][ni][hh * 2 + 1] + bias[c + 1]
                         + label_emb[(size_t)x0 * HIDDEN + c + 1] + type_emb[x1 * HIDDEN + c + 1];
                *(__half2*)(h_out + (size_t)r * HIDDEN + c) = __floats2half2_rn(v0, v1);
            }
        }
    }
}

// ---------------------------------------------------------------------------
// Fused MLP (unchanged): h16 = relu(z16 @ W1_16 + b1) @ W2_16 + b2
// ---------------------------------------------------------------------------
__global__ void __launch_bounds__(512) fused_mlp(
    const __half* __restrict__ Z,
    const __half* __restrict__ W1, const float* __restrict__ b1,
    const __half* __restrict__ W2, const float* __restrict__ b2,
    __half* __restrict__ h_out, int M)
{
    extern __shared__ __half hsm[];
    __half* sT = hsm;
    __half* sA = hsm + ST_ELEMS;
    __half* sB = hsm + ST_ELEMS + SA_ELEMS;

    const int tid  = threadIdx.x;
    const int lane = tid & 31;
    const int warp = tid >> 5;
    const int wm   = warp >> 3;
    const int wn   = warp & 7;
    const int mBase = blockIdx.x * BM;

    const int a_row = tid >> 2;
    const int a_col = (tid & 3) << 3;
    const int b_row = tid >> 4;
    const int b_col = (tid & 15) << 3;

    const int KT = HIDDEN / BK;

    float acc[4][4][4];
    #pragma unroll
    for (int i = 0; i < 4; i++)
        #pragma unroll
        for (int j = 0; j < 4; j++)
            #pragma unroll
            for (int q = 0; q < 4; q++) acc[i][j][q] = 0.f;

    auto cpA = [&](int kt, int st) {
        cp16(&sA[st * BM * SA_STRIDE + a_row * SA_STRIDE + a_col],
             Z + (size_t)(mBase + a_row) * HIDDEN + kt * BK + a_col);
    };
    auto cpB = [&](const __half* W, int kt, int st) {
        const __half* g = W + (size_t)(kt * BK + b_row) * HIDDEN + b_col;
        __half* s = &sB[st * BK * SB_STRIDE + b_row * SB_STRIDE + b_col];
        cp16(s, g);
        cp16(s + 128, g + 128);
    };
    auto compute = [&](const __half* aBase, int aStride, int aColOff, int st) {
        #pragma unroll
        for (int ks = 0; ks < 2; ks++) {
            uint32_t af[4][4], bf[2][4];
            #pragma unroll
            for (int mi = 0; mi < 4; mi++)
                ldsm_x4(af[mi], aBase
                         + (wm * 64 + mi * 16 + (lane & 15)) * aStride
                         + aColOff + ks * 16 + (lane >> 4) * 8);
            #pragma unroll
            for (int p2 = 0; p2 < 2; p2++) {
                int krow = ks * 16 + (lane & 7) + ((lane >> 3) & 1) * 8;
                int ncol = wn * 32 + p2 * 16 + (lane >> 4) * 8;
                ldsm_x4t(bf[p2], &sB[st * BK * SB_STRIDE + krow * SB_STRIDE + ncol]);
            }
            #pragma unroll
            for (int mi = 0; mi < 4; mi++)
                #pragma unroll
                for (int ni = 0; ni < 4; ni++)
                    mma16816(acc[mi][ni], af[mi],
                             bf[ni >> 1][(ni & 1) * 2 + 0], bf[ni >> 1][(ni & 1) * 2 + 1]);
        }
    };

    cpA(0, 0); cpB(W1, 0, 0); CP_COMMIT(); CP_WAIT(0); __syncthreads();
    for (int kt = 0; kt < KT; kt++) {
        const int st = kt & 1;
        if (kt + 1 < KT) { cpA(kt + 1, st ^ 1); cpB(W1, kt + 1, st ^ 1); CP_COMMIT(); }
        compute(&sA[st * BM * SA_STRIDE], SA_STRIDE, 0, st);
        if (kt + 1 < KT) CP_WAIT(0);
        __syncthreads();
    }

    #pragma unroll
    for (int mi = 0; mi < 4; mi++) {
        int rl = wm * 64 + mi * 16 + (lane >> 2);
        #pragma unroll
        for (int hh = 0; hh < 2; hh++) {
            int rr = rl + hh * 8;
            #pragma unroll
            for (int ni = 0; ni < 4; ni++) {
                int c = wn * 32 + ni * 8 + (lane & 3) * 2;
                float v0 = fmaxf(acc[mi][ni][hh * 2 + 0] + b1[c], 0.f);
                float v1 = fmaxf(acc[mi][ni][hh * 2 + 1] + b1[c + 1], 0.f);
                *(__half2*)&sT[rr * ST_STRIDE + c] = __floats2half2_rn(v0, v1);
                acc[mi][ni][hh * 2 + 0] = 0.f;
                acc[mi][ni][hh * 2 + 1] = 0.f;
            }
        }
    }

    cpB(W2, 0, 0); CP_COMMIT(); CP_WAIT(0); __syncthreads();
    for (int kt = 0; kt < KT; kt++) {
        const int st = kt & 1;
        if (kt + 1 < KT) { cpB(W2, kt + 1, st ^ 1); CP_COMMIT(); }
        compute(sT, ST_STRIDE, kt * BK, st);
        if (kt + 1 < KT) CP_WAIT(0);
        __syncthreads();
    }

    #pragma unroll
    for (int mi = 0; mi < 4; mi++) {
        int r0 = mBase + wm * 64 + mi * 16 + (lane >> 2);
        #pragma unroll
        for (int hh = 0; hh < 2; hh++) {
            int r = r0 + hh * 8;
            if (r >= M) continue;
            #pragma unroll
            for (int ni = 0; ni < 4; ni++) {
                int c = wn * 32 + ni * 8 + (lane & 3) * 2;
                float v0 = acc[mi][ni][hh * 2 + 0] + b2[c];
                float v1 = acc[mi][ni][hh * 2 + 1] + b2[c + 1];
                *(__half2*)(h_out + (size_t)r * HIDDEN + c) = __floats2half2_rn(v0, v1);
            }
        }
    }
}

// ---------------------------------------------------------------------------
// Pool (4-way row-parallel) + projection
// ---------------------------------------------------------------------------
__global__ void __launch_bounds__(512) pool_kernel(
    const __half* __restrict__ h,
    const int*    __restrict__ batch,
    float*        __restrict__ pooled)
{
    __shared__ float2 sbuf[4][128];
    int g = blockIdx.x;
    int tid = threadIdx.x;
    int rs = tid >> 7, c2 = tid & 127;

    int lo = 0, hi = N_NODES;
    while (lo < hi) { int mid = (lo + hi) >> 1; if (batch[mid] < g) lo = mid + 1; else hi = mid; }
    int start = lo;
    hi = N_NODES;
    while (lo < hi) { int mid = (lo + hi) >> 1; if (batch[mid] < g + 1) lo = mid + 1; else hi = mid; }
    int end = lo;

    float2 acc = make_float2(0.f, 0.f);
    for (int r = start + rs; r < end; r += 4) {
        float2 f = __half22float2(__ldg((const __half2*)(h + (size_t)r * HIDDEN) + c2));
        acc.x += f.x; acc.y += f.y;
    }
    sbuf[rs][c2] = acc;
    __syncthreads();
    if (rs == 0) {
        float2 s = sbuf[0][c2];
        #pragma unroll
        for (int j = 1; j < 4; j++) { s.x += sbuf[j][c2].x; s.y += sbuf[j][c2].y; }
        float inv = 1.f / fmaxf((float)(end - start), 1.f);
        *(float2*)(pooled + g * HIDDEN + c2 * 2) = make_float2(s.x * inv, s.y * inv);
    }
}

__global__ void __launch_bounds__(HIDDEN) proj_kernel(
    const float* __restrict__ pooled,
    const float* __restrict__ W,
    const float* __restrict__ b,
    float*       __restrict__ out)
{
    int g = blockIdx.x;
    int t = threadIdx.x;
    float acc = b[t];
    #pragma unroll 8
    for (int k = 0; k < HIDDEN; k++)
        acc += pooled[g * HIDDEN + k] * W[k * HIDDEN + t];
    out[g * HIDDEN + t] = acc;
}

// ---------------------------------------------------------------------------
extern "C" void kernel_launch(void* const* d_in, const int* in_sizes, int n_in,
                              void* d_out, int out_size)
{
    const int*   x        = (const int*)  d_in[0];
    const float* x_sem    = (const float*)d_in[1];
    const int*   eattr    = (const int*)  d_in[2];
    const int*   eidx     = (const int*)  d_in[3];
    const int*   batch    = (const int*)  d_in[4];
    const float* label    = (const float*)d_in[5];
    const float* type_emb = (const float*)d_in[6];
    const float* sem_W    = (const float*)d_in[7];
    const float* sem_b    = (const float*)d_in[8];
    const float* role     = (const float*)d_in[9];
    const float* child    = (const float*)d_in[10];
    const float* W1_0     = (const float*)d_in[11];
    const float* b1_0     = (const float*)d_in[12];
    const float* W2_0     = (const float*)d_in[13];
    const float* b2_0     = (const float*)d_in[14];
    const float* W1_1     = (const float*)d_in[15];
    const float* b1_1     = (const float*)d_in[16];
    const float* W2_1     = (const float*)d_in[17];
    const float* b2_1     = (const float*)d_in[18];
    const float* proj_W   = (const float*)d_in[19];
    const float* proj_b   = (const float*)d_in[20];
    float* out = (float*)d_out;

    __half *hP, *zP, *wP, *comboP;
    float *pP;
    int *degP, *offP, *curP, *srcP, *cidP, *bsP;
    cudaGetSymbolAddress((void**)&hP, g_h);
    cudaGetSymbolAddress((void**)&zP, g_z);
    cudaGetSymbolAddress((void**)&wP, g_w16);
    cudaGetSymbolAddress((void**)&comboP, g_combo);
    cudaGetSymbolAddress((void**)&pP, g_pool);
    cudaGetSymbolAddress((void**)&degP, g_deg);
    cudaGetSymbolAddress((void**)&offP, g_off);
    cudaGetSymbolAddress((void**)&curP, g_cur);
    cudaGetSymbolAddress((void**)&srcP, g_csr_src);
    cudaGetSymbolAddress((void**)&cidP, g_csr_cid);
    cudaGetSymbolAddress((void**)&bsP, g_bsum);

    __half* w_sem = wP;
    __half* w1_0  = wP + W_SEM_ELEMS;
    __half* w2_0  = w1_0 + W_HH_ELEMS;
    __half* w1_1  = w2_0 + W_HH_ELEMS;
    __half* w2_1  = w1_1 + W_HH_ELEMS;

    const int embed_smem = (ESA_ELEMS + ESB_ELEMS) * (int)sizeof(__half);   // ~44 KB
    const int fused_smem = (ST_ELEMS + SA_ELEMS + SB_ELEMS) * (int)sizeof(__half);
    cudaFuncSetAttribute(embed_gemm, cudaFuncAttributeMaxDynamicSharedMemorySize, embed_smem);
    cudaFuncSetAttribute(fused_mlp,  cudaFuncAttributeMaxDynamicSharedMemorySize, fused_smem);

    const int embed_blocks = (N_NODES + EBM - 1) / EBM;   // 1563
    const int gemm_blocks  = (N_NODES + BM - 1) / BM;     // 782
    const int node_blocks  = (N_NODES + 7) / 8;

    // Launch order: embed_gemm is MY 4th launch -> profiled.
    cvt_all_kernel<<<(CVT_TOTAL / 4 + 255) / 256, 256>>>(
        sem_W, W1_0, W2_0, W1_1, W2_1, wP, degP);                       // 1
    combo_kernel<<<N_COMBO, 128>>>(role, child, comboP);                // 2
    count_kernel<<<(N_EDGES + 255) / 256, 256>>>(eidx, degP);           // 3
    embed_gemm<<<embed_blocks, 256, embed_smem>>>(                      // 4 (PROFILED)
        x_sem, w_sem, sem_b, x, label, type_emb, hP, N_NODES, SEM_IN);

    // CSR (independent of embed result)
    scan1_kernel<<<NBLK, SCAN_B>>>(degP, offP, bsP);
    scan2_kernel<<<1, 128>>>(bsP);
    scan3_kernel<<<(N_NODES + 255) / 256, 256>>>(offP, bsP, curP);
    scatter_kernel<<<(N_EDGES + 255) / 256, 256>>>(eidx, eattr, curP, srcP, cidP);

    // GINE layer 0
    edge_csr_kernel<<<node_blocks, 256>>>(offP, degP, srcP, cidP, comboP, hP, zP);
    fused_mlp<<<gemm_blocks, 512, fused_smem>>>(zP, w1_0, b1_0, w2_0, b2_0, hP, N_NODES);

    // GINE layer 1
    edge_csr_kernel<<<node_blocks, 256>>>(offP, degP, srcP, cidP, comboP, hP, zP);
    fused_mlp<<<gemm_blocks, 512, fused_smem>>>(zP, w1_1, b1_1, w2_1, b2_1, hP, N_NODES);

    // pool + projection
    pool_kernel<<<NUM_GRAPHS, 512>>>(hP, batch, pP);
    proj_kernel<<<NUM_GRAPHS, HIDDEN>>>(pP, proj_W, proj_b, out);
}

// round 10
// speedup vs baseline: 1.2015x; 1.1013x over previous
#include <cuda_runtime.h>
#include <cuda_fp16.h>
#include <stdint.h>

#define N_NODES    100000
#define N_PAD      100096
#define N_EDGES    300000
#define NUM_GRAPHS 128
#define HIDDEN     256
#define SEM_IN     1536
#define MAX_CHILD  200
#define N_COMBO    (8 * MAX_CHILD)
#define SCAN_B     1024
#define NBLK       ((N_NODES + SCAN_B - 1) / SCAN_B)   // 98

// Scratch (zero-initialized device globals)
__device__ __align__(16) __half g_h[(size_t)N_PAD * HIDDEN];
__device__ __align__(16) __half g_z[(size_t)N_PAD * HIDDEN];
__device__ __align__(16) __half g_w16[SEM_IN * HIDDEN + 4 * HIDDEN * HIDDEN];
__device__ __align__(16) __half g_combo[(size_t)N_COMBO * HIDDEN];
__device__ float  g_pool[NUM_GRAPHS * HIDDEN];
__device__ int    g_deg[N_NODES];
__device__ int    g_off[N_NODES];
__device__ int    g_cur[N_NODES];
__device__ int    g_csr_src[N_EDGES];
__device__ int    g_csr_cid[N_EDGES];
__device__ int    g_bsum[SCAN_B];

// ---- shared tiling constants ----
#define BK 32
#define SB_STRIDE 264                  // 256 + 8 halves
#define ST_STRIDE 264

// embed: BM=64, BN=256, BK=64, 256 threads, 2 CTAs/SM
#define EBM 64
#define EBK 64
#define EKT (SEM_IN / EBK)             // 24
#define ESA_STRIDE 72                  // 64 + 8 halves
#define ESA_ELEMS (2 * EBM * ESA_STRIDE)
#define ESB_ELEMS (2 * EBK * SB_STRIDE)

// fused MLP: BM=64, BN=256, BK=32, 256 threads, 2 CTAs/SM
#define MBM 64
#define MSA_STRIDE 40                  // 32 + 8 halves
#define MST_ELEMS (MBM * ST_STRIDE)
#define MSA_ELEMS (2 * MBM * MSA_STRIDE)
#define MSB_ELEMS (2 * BK * SB_STRIDE)

// weight region sizes (elements) in g_w16
#define W_SEM_ELEMS (SEM_IN * HIDDEN)
#define W_HH_ELEMS  (HIDDEN * HIDDEN)
#define W_TOTAL     (W_SEM_ELEMS + 4 * W_HH_ELEMS)

// ---------------------------------------------------------------------------
// helpers
// ---------------------------------------------------------------------------
__device__ __forceinline__ void ldsm_x4(uint32_t* r, const __half* p) {
    uint32_t a = (uint32_t)__cvta_generic_to_shared(p);
    asm volatile("ldmatrix.sync.aligned.m8n8.x4.shared.b16 {%0,%1,%2,%3}, [%4];"
                 : "=r"(r[0]), "=r"(r[1]), "=r"(r[2]), "=r"(r[3]) : "r"(a));
}
__device__ __forceinline__ void ldsm_x4t(uint32_t* r, const __half* p) {
    uint32_t a = (uint32_t)__cvta_generic_to_shared(p);
    asm volatile("ldmatrix.sync.aligned.m8n8.x4.trans.shared.b16 {%0,%1,%2,%3}, [%4];"
                 : "=r"(r[0]), "=r"(r[1]), "=r"(r[2]), "=r"(r[3]) : "r"(a));
}
__device__ __forceinline__ void mma16816(float* c, const uint32_t* a,
                                         uint32_t b0, uint32_t b1) {
    asm volatile(
        "mma.sync.aligned.m16n8k16.row.col.f32.f16.f16.f32 "
        "{%0,%1,%2,%3}, {%4,%5,%6,%7}, {%8,%9}, {%0,%1,%2,%3};"
        : "+f"(c[0]), "+f"(c[1]), "+f"(c[2]), "+f"(c[3])
        : "r"(a[0]), "r"(a[1]), "r"(a[2]), "r"(a[3]), "r"(b0), "r"(b1));
}
__device__ __forceinline__ void cp16(void* smem_dst, const void* gsrc) {
    uint32_t s = (uint32_t)__cvta_generic_to_shared(smem_dst);
    asm volatile("cp.async.cg.shared.global [%0], [%1], 16;" :: "r"(s), "l"(gsrc));
}
#define CP_COMMIT() asm volatile("cp.async.commit_group;")
#define CP_WAIT(N)  asm volatile("cp.async.wait_group %0;" :: "n"(N))

// ---------------------------------------------------------------------------
// setup: one kernel converts all weights to fp16 AND zeroes deg.
// ---------------------------------------------------------------------------
#define CVT_TOTAL   (W_TOTAL + N_NODES + 24)
__global__ void cvt_all_kernel(const float* __restrict__ sem_W,
                               const float* __restrict__ W1_0, const float* __restrict__ W2_0,
                               const float* __restrict__ W1_1, const float* __restrict__ W2_1,
                               __half* __restrict__ dst, int* __restrict__ deg)
{
    int e = (blockIdx.x * blockDim.x + threadIdx.x) * 4;
    if (e < W_TOTAL) {
        const float* src;
        int local = e;
        if (local < W_SEM_ELEMS) { src = sem_W; }
        else {
            local -= W_SEM_ELEMS;
            int w = local / W_HH_ELEMS;
            local -= w * W_HH_ELEMS;
            src = (w == 0) ? W1_0 : (w == 1) ? W2_0 : (w == 2) ? W1_1 : W2_1;
        }
        float4 v = *(const float4*)(src + local);
        __half2* d = (__half2*)(dst + e);
        d[0] = __floats2half2_rn(v.x, v.y);
        d[1] = __floats2half2_rn(v.z, v.w);
    } else {
        int i = e - W_TOTAL;
        #pragma unroll
        for (int j = 0; j < 4; j++)
            if (i + j < N_NODES) deg[i + j] = 0;
    }
}

__global__ void combo_kernel(const float* __restrict__ role, const float* __restrict__ child,
                             __half* __restrict__ combo) {
    int rc = blockIdx.x;
    int r = rc / MAX_CHILD, cc = rc % MAX_CHILD;
    int t = threadIdx.x;
    float2 a = *(const float2*)(role + r * HIDDEN + t * 2);
    float2 b = *(const float2*)(child + cc * HIDDEN + t * 2);
    *(__half2*)(combo + (size_t)rc * HIDDEN + t * 2) = __floats2half2_rn(a.x + b.x, a.y + b.y);
}

// ---------------------------------------------------------------------------
// CSR build
// ---------------------------------------------------------------------------
__global__ void count_kernel(const int* __restrict__ eidx, int* __restrict__ deg) {
    int e = blockIdx.x * blockDim.x + threadIdx.x;
    if (e < N_EDGES) atomicAdd(&deg[eidx[N_EDGES + e]], 1);
}
__global__ void __launch_bounds__(SCAN_B) scan1_kernel(
    const int* __restrict__ deg, int* __restrict__ off, int* __restrict__ bsum)
{
    __shared__ int s[SCAN_B];
    int tid = threadIdx.x;
    int i = blockIdx.x * SCAN_B + tid;
    int v = (i < N_NODES) ? deg[i] : 0;
    s[tid] = v; __syncthreads();
    #pragma unroll
    for (int d = 1; d < SCAN_B; d <<= 1) {
        int t = (tid >= d) ? s[tid - d] : 0;
        __syncthreads();
        if (tid >= d) s[tid] += t;
        __syncthreads();
    }
    if (i < N_NODES) off[i] = s[tid] - v;
    if (tid == SCAN_B - 1) bsum[blockIdx.x] = s[tid];
}
__global__ void __launch_bounds__(128) scan2_kernel(int* bsum) {
    __shared__ int s[128];
    int tid = threadIdx.x;
    int v = (tid < NBLK) ? bsum[tid] : 0;
    s[tid] = v; __syncthreads();
    #pragma unroll
    for (int d = 1; d < 128; d <<= 1) {
        int t = (tid >= d) ? s[tid - d] : 0;
        __syncthreads();
        if (tid >= d) s[tid] += t;
        __syncthreads();
    }
    if (tid < NBLK) bsum[tid] = s[tid] - v;
}
__global__ void scan3_kernel(int* __restrict__ off, const int* __restrict__ bsum,
                             int* __restrict__ cur) {
    int i = blockIdx.x * blockDim.x + threadIdx.x;
    if (i < N_NODES) {
        int o = off[i] + bsum[i >> 10];
        off[i] = o;
        cur[i] = o;
    }
}
__global__ void scatter_kernel(const int* __restrict__ eidx, const int* __restrict__ eattr,
                               int* __restrict__ cur,
                               int* __restrict__ csr_src, int* __restrict__ csr_cid) {
    int e = blockIdx.x * blockDim.x + threadIdx.x;
    if (e < N_EDGES) {
        int pos = atomicAdd(&cur[eidx[N_EDGES + e]], 1);
        csr_src[pos] = eidx[e];
        int r  = eattr[2 * e];
        int cc = min(max(eattr[2 * e + 1], 0), MAX_CHILD - 1);
        csr_cid[pos] = r * MAX_CHILD + cc;
    }
}

// ---------------------------------------------------------------------------
// Edge aggregation (round-6 measured-good form): one warp per dst node, unroll-2.
// ---------------------------------------------------------------------------
__global__ void __launch_bounds__(256) edge_csr_kernel(
    const int*    __restrict__ off,
    const int*    __restrict__ deg,
    const int*    __restrict__ csr_src,
    const int*    __restrict__ csr_cid,
    const __half* __restrict__ combo,
    const __half* __restrict__ h,
    __half*       __restrict__ z)
{
    int n = blockIdx.x * 8 + (threadIdx.x >> 5);
    if (n >= N_NODES) return;
    int lane = threadIdx.x & 31;

    float4 hv = __ldg((const float4*)(h + (size_t)n * HIDDEN) + lane);
    __half2* hp = (__half2*)&hv;
    float2 a0 = __half22float2(hp[0]), a1 = __half22float2(hp[1]);
    float2 a2 = __half22float2(hp[2]), a3 = __half22float2(hp[3]);
    float acc[8] = {a0.x, a0.y, a1.x, a1.y, a2.x, a2.y, a3.x, a3.y};

    int start = off[n];
    int d = deg[n];
    int k = 0;

    for (; k + 2 <= d; k += 2) {
        int s0 = __ldg(&csr_src[start + k]);
        int c0 = __ldg(&csr_cid[start + k]);
        int s1 = __ldg(&csr_src[start + k + 1]);
        int c1 = __ldg(&csr_cid[start + k + 1]);

        float4 sv0 = __ldg((const float4*)(h + (size_t)s0 * HIDDEN) + lane);
        float4 cv0 = __ldg((const float4*)(combo + (size_t)c0 * HIDDEN) + lane);
        float4 sv1 = __ldg((const float4*)(h + (size_t)s1 * HIDDEN) + lane);
        float4 cv1 = __ldg((const float4*)(combo + (size_t)c1 * HIDDEN) + lane);

        __half2* sp0 = (__half2*)&sv0; __half2* cp0 = (__half2*)&cv0;
        __half2* sp1 = (__half2*)&sv1; __half2* cp1 = (__half2*)&cv1;
        #pragma unroll
        for (int j = 0; j < 4; j++) {
            float2 f0 = __half22float2(sp0[j]);
            float2 g0 = __half22float2(cp0[j]);
            float2 f1 = __half22float2(sp1[j]);
            float2 g1 = __half22float2(cp1[j]);
            acc[2 * j + 0] += fmaxf(f0.x + g0.x, 0.f) + fmaxf(f1.x + g1.x, 0.f);
            acc[2 * j + 1] += fmaxf(f0.y + g0.y, 0.f) + fmaxf(f1.y + g1.y, 0.f);
        }
    }
    if (k < d) {
        int s0 = __ldg(&csr_src[start + k]);
        int c0 = __ldg(&csr_cid[start + k]);
        float4 sv0 = __ldg((const float4*)(h + (size_t)s0 * HIDDEN) + lane);
        float4 cv0 = __ldg((const float4*)(combo + (size_t)c0 * HIDDEN) + lane);
        __half2* sp0 = (__half2*)&sv0; __half2* cp0 = (__half2*)&cv0;
        #pragma unroll
        for (int j = 0; j < 4; j++) {
            float2 f0 = __half22float2(sp0[j]);
            float2 g0 = __half22float2(cp0[j]);
            acc[2 * j + 0] += fmaxf(f0.x + g0.x, 0.f);
            acc[2 * j + 1] += fmaxf(f0.y + g0.y, 0.f);
        }
    }

    float4 outv;
    __half2* op = (__half2*)&outv;
    op[0] = __floats2half2_rn(acc[0], acc[1]);
    op[1] = __floats2half2_rn(acc[2], acc[3]);
    op[2] = __floats2half2_rn(acc[4], acc[5]);
    op[3] = __floats2half2_rn(acc[6], acc[7]);
    ((float4*)(z + (size_t)n * HIDDEN))[lane] = outv;
}

// ---------------------------------------------------------------------------
// Embed GEMM: BM=64, BN=256, BK=64, 256 threads, 2 CTAs/SM.
// 8 warps as 2x4, warp tile 32x64, acc[2][8][4]=64 regs, 4 ks-steps per sync.
// ---------------------------------------------------------------------------
__global__ void __launch_bounds__(256, 2) embed_gemm(
    const float* __restrict__ A, const __half* __restrict__ B,
    const float* __restrict__ bias,
    const int*   __restrict__ xidx,
    const float* __restrict__ label_emb,
    const float* __restrict__ type_emb,
    __half* __restrict__ h_out, int M)
{
    extern __shared__ __half smem[];
    __half* sA = smem;                 // 2 x EBM x ESA_STRIDE
    __half* sB = smem + ESA_ELEMS;     // 2 x EBK x SB_STRIDE

    const int tid  = threadIdx.x;
    const int lane = tid & 31;
    const int warp = tid >> 5;
    const int wm   = warp >> 2;        // 0..1 -> 32-row span
    const int wn   = warp & 3;         // 0..3 -> 64-col span
    const int mBase = blockIdx.x * EBM;

    float4 ra[4];
    float acc[2][8][4];
    #pragma unroll
    for (int i = 0; i < 2; i++)
        #pragma unroll
        for (int j = 0; j < 8; j++)
            #pragma unroll
            for (int q = 0; q < 4; q++) acc[i][j][q] = 0.f;

    auto ldgA = [&](int kt) {
        #pragma unroll
        for (int i = 0; i < 4; i++) {
            int idx = tid + i * 256;              // 0..1023
            int row = idx >> 4;                   // 0..63
            int c4  = (idx & 15) << 2;            // float col 0..60
            int r = mBase + row;
            if (r < M) ra[i] = *(const float4*)(A + (size_t)r * SEM_IN + kt * EBK + c4);
            else       ra[i] = make_float4(0.f, 0.f, 0.f, 0.f);
        }
    };
    auto stsA = [&](int st) {
        #pragma unroll
        for (int i = 0; i < 4; i++) {
            int idx = tid + i * 256;
            int row = idx >> 4;
            int hc  = (idx & 15) << 2;            // half col 0..60
            __half2* p = (__half2*)&sA[st * EBM * ESA_STRIDE + row * ESA_STRIDE + hc];
            p[0] = __floats2half2_rn(ra[i].x, ra[i].y);
            p[1] = __floats2half2_rn(ra[i].z, ra[i].w);
        }
    };
    auto cpB = [&](int kt, int st) {
        // 64 rows x 32 chunks(16B) = 2048 chunks; 256 thr x 8
        #pragma unroll
        for (int i = 0; i < 8; i++) {
            int idx = tid + i * 256;
            int row = idx >> 5;                   // 0..63
            int ch  = idx & 31;
            cp16(&sB[st * EBK * SB_STRIDE + row * SB_STRIDE + ch * 8],
                 B + (size_t)(kt * EBK + row) * HIDDEN + ch * 8);
        }
    };

    ldgA(0); cpB(0, 0); CP_COMMIT();
    stsA(0); CP_WAIT(0); __syncthreads();

    for (int kt = 0; kt < EKT; kt++) {
        const int st = kt & 1;
        if (kt + 1 < EKT) { ldgA(kt + 1); cpB(kt + 1, st ^ 1); CP_COMMIT(); }
        #pragma unroll
        for (int ks = 0; ks < 4; ks++) {
            uint32_t af[2][4], bf[4][4];
            #pragma unroll
            for (int mi = 0; mi < 2; mi++)
                ldsm_x4(af[mi], &sA[st * EBM * ESA_STRIDE
                         + (wm * 32 + mi * 16 + (lane & 15)) * ESA_STRIDE
                         + ks * 16 + (lane >> 4) * 8]);
            #pragma unroll
            for (int p2 = 0; p2 < 4; p2++) {
                int krow = ks * 16 + (lane & 7) + ((lane >> 3) & 1) * 8;
                int ncol = wn * 64 + p2 * 16 + (lane >> 4) * 8;
                ldsm_x4t(bf[p2], &sB[st * EBK * SB_STRIDE + krow * SB_STRIDE + ncol]);
            }
            #pragma unroll
            for (int mi = 0; mi < 2; mi++)
                #pragma unroll
                for (int ni = 0; ni < 8; ni++)
                    mma16816(acc[mi][ni], af[mi],
                             bf[ni >> 1][(ni & 1) * 2 + 0], bf[ni >> 1][(ni & 1) * 2 + 1]);
        }
        if (kt + 1 < EKT) { stsA(st ^ 1); CP_WAIT(0); }
        __syncthreads();
    }

    #pragma unroll
    for (int mi = 0; mi < 2; mi++) {
        int r0 = mBase + wm * 32 + mi * 16 + (lane >> 2);
        #pragma unroll
        for (int hh = 0; hh < 2; hh++) {
            int r = r0 + hh * 8;
            if (r >= M) continue;
            int x0 = xidx[2 * r], x1 = xidx[2 * r + 1];
            #pragma unroll
            for (int ni = 0; ni < 8; ni++) {
                int c = wn * 64 + ni * 8 + (lane & 3) * 2;
                float v0 = acc[mi][ni][hh * 2 + 0] + bias[c]
                         + label_emb[(size_t)x0 * HIDDEN + c] + type_emb[x1 * HIDDEN + c];
                float v1 = acc[mi][ni][hh * 2 + 1] + bias[c + 1]
                         + label_emb[(size_t)x0 * HIDDEN + c + 1] + type_emb[x1 * HIDDEN + c + 1];
                *(__half2*)(h_out + (size_t)r * HIDDEN + c) = __floats2half2_rn(v0, v1);
            }
        }
    }
}

// ---------------------------------------------------------------------------
// Fused MLP: BM=64, BN=256, BK=32, 256 threads, 2 CTAs/SM.
// h16 = relu(z16 @ W1 + b1) @ W2 + b2, t staged in smem (64 x 256 fp16).
// ---------------------------------------------------------------------------
__global__ void __launch_bounds__(256, 2) fused_mlp(
    const __half* __restrict__ Z,
    const __half* __restrict__ W1, const float* __restrict__ b1,
    const __half* __restrict__ W2, const float* __restrict__ b2,
    __half* __restrict__ h_out, int M)
{
    extern __shared__ __half hsm[];
    __half* sT = hsm;                          // MBM x ST_STRIDE
    __half* sA = hsm + MST_ELEMS;              // 2 x MBM x MSA_STRIDE
    __half* sB = hsm + MST_ELEMS + MSA_ELEMS;  // 2 x BK x SB_STRIDE

    const int tid  = threadIdx.x;
    const int lane = tid & 31;
    const int warp = tid >> 5;
    const int wm   = warp >> 2;        // 0..1
    const int wn   = warp & 3;         // 0..3
    const int mBase = blockIdx.x * MBM;

    const int KT = HIDDEN / BK;        // 8

    float acc[2][8][4];
    #pragma unroll
    for (int i = 0; i < 2; i++)
        #pragma unroll
        for (int j = 0; j < 8; j++)
            #pragma unroll
            for (int q = 0; q < 4; q++) acc[i][j][q] = 0.f;

    auto cpA = [&](int kt, int st) {
        // FIXED: 64 rows x 4 chunks(16B) = 256 chunks; all 256 threads
        int row = tid >> 2;
        int ch  = tid & 3;
        cp16(&sA[st * MBM * MSA_STRIDE + row * MSA_STRIDE + ch * 8],
             Z + (size_t)(mBase + row) * HIDDEN + kt * BK + ch * 8);
    };
    auto cpB = [&](const __half* W, int kt, int st) {
        // 32 rows x 32 chunks = 1024 chunks; 256 thr x 4
        #pragma unroll
        for (int i = 0; i < 4; i++) {
            int idx = tid + i * 256;
            int row = idx >> 5;
            int ch  = idx & 31;
            cp16(&sB[st * BK * SB_STRIDE + row * SB_STRIDE + ch * 8],
                 W + (size_t)(kt * BK + row) * HIDDEN + ch * 8);
        }
    };
    auto compute = [&](const __half* aBase, int aStride, int aColOff, int st) {
        #pragma unroll
        for (int ks = 0; ks < 2; ks++) {
            uint32_t af[2][4], bf[4][4];
            #pragma unroll
            for (int mi = 0; mi < 2; mi++)
                ldsm_x4(af[mi], aBase
                         + (wm * 32 + mi * 16 + (lane & 15)) * aStride
                         + aColOff + ks * 16 + (lane >> 4) * 8);
            #pragma unroll
            for (int p2 = 0; p2 < 4; p2++) {
                int krow = ks * 16 + (lane & 7) + ((lane >> 3) & 1) * 8;
                int ncol = wn * 64 + p2 * 16 + (lane >> 4) * 8;
                ldsm_x4t(bf[p2], &sB[st * BK * SB_STRIDE + krow * SB_STRIDE + ncol]);
            }
            #pragma unroll
            for (int mi = 0; mi < 2; mi++)
                #pragma unroll
                for (int ni = 0; ni < 8; ni++)
                    mma16816(acc[mi][ni], af[mi],
                             bf[ni >> 1][(ni & 1) * 2 + 0], bf[ni >> 1][(ni & 1) * 2 + 1]);
        }
    };

    // ---- Stage 1: t = relu(Z @ W1 + b1) -> sT ----
    cpA(0, 0); cpB(W1, 0, 0); CP_COMMIT(); CP_WAIT(0); __syncthreads();
    for (int kt = 0; kt < KT; kt++) {
        const int st = kt & 1;
        if (kt + 1 < KT) { cpA(kt + 1, st ^ 1); cpB(W1, kt + 1, st ^ 1); CP_COMMIT(); }
        compute(&sA[st * MBM * MSA_STRIDE], MSA_STRIDE, 0, st);
        if (kt + 1 < KT) CP_WAIT(0);
        __syncthreads();
    }

    // epilogue 1: relu(+b1) -> sT, reset acc
    #pragma unroll
    for (int mi = 0; mi < 2; mi++) {
        int rl = wm * 32 + mi * 16 + (lane >> 2);
        #pragma unroll
        for (int hh = 0; hh < 2; hh++) {
            int rr = rl + hh * 8;
            #pragma unroll
            for (int ni = 0; ni < 8; ni++) {
                int c = wn * 64 + ni * 8 + (lane & 3) * 2;
                float v0 = fmaxf(acc[mi][ni][hh * 2 + 0] + b1[c], 0.f);
                float v1 = fmaxf(acc[mi][ni][hh * 2 + 1] + b1[c + 1], 0.f);
                *(__half2*)&sT[rr * ST_STRIDE + c] = __floats2half2_rn(v0, v1);
                acc[mi][ni][hh * 2 + 0] = 0.f;
                acc[mi][ni][hh * 2 + 1] = 0.f;
            }
        }
    }

    // ---- Stage 2: out = t @ W2 + b2 ----
    cpB(W2, 0, 0); CP_COMMIT(); CP_WAIT(0); __syncthreads();
    for (int kt = 0; kt < KT; kt++) {
        const int st = kt & 1;
        if (kt + 1 < KT) { cpB(W2, kt + 1, st ^ 1); CP_COMMIT(); }
        compute(sT, ST_STRIDE, kt * BK, st);
        if (kt + 1 < KT) CP_WAIT(0);
        __syncthreads();
    }

    #pragma unroll
    for (int mi = 0; mi < 2; mi++) {
        int r0 = mBase + wm * 32 + mi * 16 + (lane >> 2);
        #pragma unroll
        for (int hh = 0; hh < 2; hh++) {
            int r = r0 + hh * 8;
            if (r >= M) continue;
            #pragma unroll
            for (int ni = 0; ni < 8; ni++) {
                int c = wn * 64 + ni * 8 + (lane & 3) * 2;
                float v0 = acc[mi][ni][hh * 2 + 0] + b2[c];
                float v1 = acc[mi][ni][hh * 2 + 1] + b2[c + 1];
                *(__half2*)(h_out + (size_t)r * HIDDEN + c) = __floats2half2_rn(v0, v1);
            }
        }
    }
}

// ---------------------------------------------------------------------------
// Pool (4-way row-parallel) + projection
// ---------------------------------------------------------------------------
__global__ void __launch_bounds__(512) pool_kernel(
    const __half* __restrict__ h,
    const int*    __restrict__ batch,
    float*        __restrict__ pooled)
{
    __shared__ float2 sbuf[4][128];
    int g = blockIdx.x;
    int tid = threadIdx.x;
    int rs = tid >> 7, c2 = tid & 127;

    int lo = 0, hi = N_NODES;
    while (lo < hi) { int mid = (lo + hi) >> 1; if (batch[mid] < g) lo = mid + 1; else hi = mid; }
    int start = lo;
    hi = N_NODES;
    while (lo < hi) { int mid = (lo + hi) >> 1; if (batch[mid] < g + 1) lo = mid + 1; else hi = mid; }
    int end = lo;

    float2 acc = make_float2(0.f, 0.f);
    for (int r = start + rs; r < end; r += 4) {
        float2 f = __half22float2(__ldg((const __half2*)(h + (size_t)r * HIDDEN) + c2));
        acc.x += f.x; acc.y += f.y;
    }
    sbuf[rs][c2] = acc;
    __syncthreads();
    if (rs == 0) {
        float2 s = sbuf[0][c2];
        #pragma unroll
        for (int j = 1; j < 4; j++) { s.x += sbuf[j][c2].x; s.y += sbuf[j][c2].y; }
        float inv = 1.f / fmaxf((float)(end - start), 1.f);
        *(float2*)(pooled + g * HIDDEN + c2 * 2) = make_float2(s.x * inv, s.y * inv);
    }
}

__global__ void __launch_bounds__(HIDDEN) proj_kernel(
    const float* __restrict__ pooled,
    const float* __restrict__ W,
    const float* __restrict__ b,
    float*       __restrict__ out)
{
    int g = blockIdx.x;
    int t = threadIdx.x;
    float acc = b[t];
    #pragma unroll 8
    for (int k = 0; k < HIDDEN; k++)
        acc += pooled[g * HIDDEN + k] * W[k * HIDDEN + t];
    out[g * HIDDEN + t] = acc;
}

// ---------------------------------------------------------------------------
extern "C" void kernel_launch(void* const* d_in, const int* in_sizes, int n_in,
                              void* d_out, int out_size)
{
    const int*   x        = (const int*)  d_in[0];
    const float* x_sem    = (const float*)d_in[1];
    const int*   eattr    = (const int*)  d_in[2];
    const int*   eidx     = (const int*)  d_in[3];
    const int*   batch    = (const int*)  d_in[4];
    const float* label    = (const float*)d_in[5];
    const float* type_emb = (const float*)d_in[6];
    const float* sem_W    = (const float*)d_in[7];
    const float* sem_b    = (const float*)d_in[8];
    const float* role     = (const float*)d_in[9];
    const float* child    = (const float*)d_in[10];
    const float* W1_0     = (const float*)d_in[11];
    const float* b1_0     = (const float*)d_in[12];
    const float* W2_0     = (const float*)d_in[13];
    const float* b2_0     = (const float*)d_in[14];
    const float* W1_1     = (const float*)d_in[15];
    const float* b1_1     = (const float*)d_in[16];
    const float* W2_1     = (const float*)d_in[17];
    const float* b2_1     = (const float*)d_in[18];
    const float* proj_W   = (const float*)d_in[19];
    const float* proj_b   = (const float*)d_in[20];
    float* out = (float*)d_out;

    __half *hP, *zP, *wP, *comboP;
    float *pP;
    int *degP, *offP, *curP, *srcP, *cidP, *bsP;
    cudaGetSymbolAddress((void**)&hP, g_h);
    cudaGetSymbolAddress((void**)&zP, g_z);
    cudaGetSymbolAddress((void**)&wP, g_w16);
    cudaGetSymbolAddress((void**)&comboP, g_combo);
    cudaGetSymbolAddress((void**)&pP, g_pool);
    cudaGetSymbolAddress((void**)&degP, g_deg);
    cudaGetSymbolAddress((void**)&offP, g_off);
    cudaGetSymbolAddress((void**)&curP, g_cur);
    cudaGetSymbolAddress((void**)&srcP, g_csr_src);
    cudaGetSymbolAddress((void**)&cidP, g_csr_cid);
    cudaGetSymbolAddress((void**)&bsP, g_bsum);

    __half* w_sem = wP;
    __half* w1_0  = wP + W_SEM_ELEMS;
    __half* w2_0  = w1_0 + W_HH_ELEMS;
    __half* w1_1  = w2_0 + W_HH_ELEMS;
    __half* w2_1  = w1_1 + W_HH_ELEMS;

    const int embed_smem = (ESA_ELEMS + ESB_ELEMS) * (int)sizeof(__half);        // ~86 KB
    const int fused_smem = (MST_ELEMS + MSA_ELEMS + MSB_ELEMS) * (int)sizeof(__half); // ~78 KB
    cudaFuncSetAttribute(embed_gemm, cudaFuncAttributeMaxDynamicSharedMemorySize, embed_smem);
    cudaFuncSetAttribute(fused_mlp,  cudaFuncAttributeMaxDynamicSharedMemorySize, fused_smem);

    const int embed_blocks = (N_NODES + EBM - 1) / EBM;   // 1563
    const int mlp_blocks   = (N_NODES + MBM - 1) / MBM;   // 1563
    const int node_blocks  = (N_NODES + 7) / 8;

    // Launch order: embed_gemm is MY 4th launch -> profiled.
    cvt_all_kernel<<<(CVT_TOTAL / 4 + 255) / 256, 256>>>(
        sem_W, W1_0, W2_0, W1_1, W2_1, wP, degP);                       // 1
    combo_kernel<<<N_COMBO, 128>>>(role, child, comboP);                // 2
    count_kernel<<<(N_EDGES + 255) / 256, 256>>>(eidx, degP);           // 3
    embed_gemm<<<embed_blocks, 256, embed_smem>>>(                      // 4 (PROFILED)
        x_sem, w_sem, sem_b, x, label, type_emb, hP, N_NODES);

    // CSR (independent of embed result)
    scan1_kernel<<<NBLK, SCAN_B>>>(degP, offP, bsP);
    scan2_kernel<<<1, 128>>>(bsP);
    scan3_kernel<<<(N_NODES + 255) / 256, 256>>>(offP, bsP, curP);
    scatter_kernel<<<(N_EDGES + 255) / 256, 256>>>(eidx, eattr, curP, srcP, cidP);

    // GINE layer 0
    edge_csr_kernel<<<node_blocks, 256>>>(offP, degP, srcP, cidP, comboP, hP, zP);
    fused_mlp<<<mlp_blocks, 256, fused_smem>>>(zP, w1_0, b1_0, w2_0, b2_0, hP, N_NODES);

    // GINE layer 1
    edge_csr_kernel<<<node_blocks, 256>>>(offP, degP, srcP, cidP, comboP, hP, zP);
    fused_mlp<<<mlp_blocks, 256, fused_smem>>>(zP, w1_1, b1_1, w2_1, b2_1, hP, N_NODES);

    // pool + projection
    pool_kernel<<<NUM_GRAPHS, 512>>>(hP, batch, pP);
    proj_kernel<<<NUM_GRAPHS, HIDDEN>>>(pP, proj_W, proj_b, out);
}

// round 11
// speedup vs baseline: 1.2284x; 1.0224x over previous
#include <cuda_runtime.h>
#include <cuda_fp16.h>
#include <stdint.h>

#define N_NODES    100000
#define N_PAD      100096
#define N_EDGES    300000
#define NUM_GRAPHS 128
#define HIDDEN     256
#define SEM_IN     1536
#define MAX_CHILD  200
#define N_COMBO    (8 * MAX_CHILD)
#define SCAN_B     1024
#define NBLK       ((N_NODES + SCAN_B - 1) / SCAN_B)   // 98

// Scratch (zero-initialized device globals)
__device__ __align__(16) __half g_h[(size_t)N_PAD * HIDDEN];
__device__ __align__(16) __half g_z[(size_t)N_PAD * HIDDEN];
__device__ __align__(16) __half g_w16[SEM_IN * HIDDEN + 4 * HIDDEN * HIDDEN];
__device__ __align__(16) __half g_combo[(size_t)N_COMBO * HIDDEN];
__device__ float  g_pool[NUM_GRAPHS * HIDDEN];
__device__ int    g_deg[N_NODES];
__device__ int    g_off[N_NODES];
__device__ int    g_cur[N_NODES];
__device__ int    g_csr_src[N_EDGES];
__device__ int    g_csr_cid[N_EDGES];
__device__ int    g_bsum[SCAN_B];

// ---- shared tiling constants ----
#define BK 32
#define SB_STRIDE 264                  // 256 + 8 halves
#define ST_STRIDE 264

// embed: BM=64, BN=256, BK=64, 256 threads, 2 CTAs/SM
#define EBM 64
#define EBK 64
#define EKT (SEM_IN / EBK)             // 24
#define ESA_STRIDE 72                  // 64 + 8 halves
#define ESA_ELEMS (2 * EBM * ESA_STRIDE)
#define ESB_ELEMS (2 * EBK * SB_STRIDE)

// fused MLP: BM=64, BN=256, BK=32, 256 threads, 2 CTAs/SM
#define MBM 64
#define MSA_STRIDE 40                  // 32 + 8 halves
#define MST_ELEMS (MBM * ST_STRIDE)
#define MSA_ELEMS (2 * MBM * MSA_STRIDE)
#define MSB_ELEMS (2 * BK * SB_STRIDE)

// weight region sizes (elements) in g_w16
#define W_SEM_ELEMS (SEM_IN * HIDDEN)
#define W_HH_ELEMS  (HIDDEN * HIDDEN)
#define W_TOTAL     (W_SEM_ELEMS + 4 * W_HH_ELEMS)

// ---------------------------------------------------------------------------
// helpers
// ---------------------------------------------------------------------------
__device__ __forceinline__ void ldsm_x4(uint32_t* r, const __half* p) {
    uint32_t a = (uint32_t)__cvta_generic_to_shared(p);
    asm volatile("ldmatrix.sync.aligned.m8n8.x4.shared.b16 {%0,%1,%2,%3}, [%4];"
                 : "=r"(r[0]), "=r"(r[1]), "=r"(r[2]), "=r"(r[3]) : "r"(a));
}
__device__ __forceinline__ void ldsm_x4t(uint32_t* r, const __half* p) {
    uint32_t a = (uint32_t)__cvta_generic_to_shared(p);
    asm volatile("ldmatrix.sync.aligned.m8n8.x4.trans.shared.b16 {%0,%1,%2,%3}, [%4];"
                 : "=r"(r[0]), "=r"(r[1]), "=r"(r[2]), "=r"(r[3]) : "r"(a));
}
__device__ __forceinline__ void mma16816(float* c, const uint32_t* a,
                                         uint32_t b0, uint32_t b1) {
    asm volatile(
        "mma.sync.aligned.m16n8k16.row.col.f32.f16.f16.f32 "
        "{%0,%1,%2,%3}, {%4,%5,%6,%7}, {%8,%9}, {%0,%1,%2,%3};"
        : "+f"(c[0]), "+f"(c[1]), "+f"(c[2]), "+f"(c[3])
        : "r"(a[0]), "r"(a[1]), "r"(a[2]), "r"(a[3]), "r"(b0), "r"(b1));
}
__device__ __forceinline__ void cp16(void* smem_dst, const void* gsrc) {
    uint32_t s = (uint32_t)__cvta_generic_to_shared(smem_dst);
    asm volatile("cp.async.cg.shared.global [%0], [%1], 16;" :: "r"(s), "l"(gsrc));
}
__device__ __forceinline__ void cp16_raw(uint32_t smem_addr, const void* gsrc) {
    asm volatile("cp.async.cg.shared.global [%0], [%1], 16;" :: "r"(smem_addr), "l"(gsrc));
}
#define CP_COMMIT() asm volatile("cp.async.commit_group;")
#define CP_WAIT(N)  asm volatile("cp.async.wait_group %0;" :: "n"(N))

// ---------------------------------------------------------------------------
// setup: one kernel converts all weights to fp16 AND zeroes deg.
// ---------------------------------------------------------------------------
#define CVT_TOTAL   (W_TOTAL + N_NODES + 24)
__global__ void cvt_all_kernel(const float* __restrict__ sem_W,
                               const float* __restrict__ W1_0, const float* __restrict__ W2_0,
                               const float* __restrict__ W1_1, const float* __restrict__ W2_1,
                               __half* __restrict__ dst, int* __restrict__ deg)
{
    int e = (blockIdx.x * blockDim.x + threadIdx.x) * 4;
    if (e < W_TOTAL) {
        const float* src;
        int local = e;
        if (local < W_SEM_ELEMS) { src = sem_W; }
        else {
            local -= W_SEM_ELEMS;
            int w = local / W_HH_ELEMS;
            local -= w * W_HH_ELEMS;
            src = (w == 0) ? W1_0 : (w == 1) ? W2_0 : (w == 2) ? W1_1 : W2_1;
        }
        float4 v = *(const float4*)(src + local);
        __half2* d = (__half2*)(dst + e);
        d[0] = __floats2half2_rn(v.x, v.y);
        d[1] = __floats2half2_rn(v.z, v.w);
    } else {
        int i = e - W_TOTAL;
        #pragma unroll
        for (int j = 0; j < 4; j++)
            if (i + j < N_NODES) deg[i + j] = 0;
    }
}

__global__ void combo_kernel(const float* __restrict__ role, const float* __restrict__ child,
                             __half* __restrict__ combo) {
    int rc = blockIdx.x;
    int r = rc / MAX_CHILD, cc = rc % MAX_CHILD;
    int t = threadIdx.x;
    float2 a = *(const float2*)(role + r * HIDDEN + t * 2);
    float2 b = *(const float2*)(child + cc * HIDDEN + t * 2);
    *(__half2*)(combo + (size_t)rc * HIDDEN + t * 2) = __floats2half2_rn(a.x + b.x, a.y + b.y);
}

// ---------------------------------------------------------------------------
// CSR build
// ---------------------------------------------------------------------------
__global__ void count_kernel(const int* __restrict__ eidx, int* __restrict__ deg) {
    int e = blockIdx.x * blockDim.x + threadIdx.x;
    if (e < N_EDGES) atomicAdd(&deg[eidx[N_EDGES + e]], 1);
}
__global__ void __launch_bounds__(SCAN_B) scan1_kernel(
    const int* __restrict__ deg, int* __restrict__ off, int* __restrict__ bsum)
{
    __shared__ int s[SCAN_B];
    int tid = threadIdx.x;
    int i = blockIdx.x * SCAN_B + tid;
    int v = (i < N_NODES) ? deg[i] : 0;
    s[tid] = v; __syncthreads();
    #pragma unroll
    for (int d = 1; d < SCAN_B; d <<= 1) {
        int t = (tid >= d) ? s[tid - d] : 0;
        __syncthreads();
        if (tid >= d) s[tid] += t;
        __syncthreads();
    }
    if (i < N_NODES) off[i] = s[tid] - v;
    if (tid == SCAN_B - 1) bsum[blockIdx.x] = s[tid];
}
__global__ void __launch_bounds__(128) scan2_kernel(int* bsum) {
    __shared__ int s[128];
    int tid = threadIdx.x;
    int v = (tid < NBLK) ? bsum[tid] : 0;
    s[tid] = v; __syncthreads();
    #pragma unroll
    for (int d = 1; d < 128; d <<= 1) {
        int t = (tid >= d) ? s[tid - d] : 0;
        __syncthreads();
        if (tid >= d) s[tid] += t;
        __syncthreads();
    }
    if (tid < NBLK) bsum[tid] = s[tid] - v;
}
__global__ void scan3_kernel(int* __restrict__ off, const int* __restrict__ bsum,
                             int* __restrict__ cur) {
    int i = blockIdx.x * blockDim.x + threadIdx.x;
    if (i < N_NODES) {
        int o = off[i] + bsum[i >> 10];
        off[i] = o;
        cur[i] = o;
    }
}
__global__ void scatter_kernel(const int* __restrict__ eidx, const int* __restrict__ eattr,
                               int* __restrict__ cur,
                               int* __restrict__ csr_src, int* __restrict__ csr_cid) {
    int e = blockIdx.x * blockDim.x + threadIdx.x;
    if (e < N_EDGES) {
        int pos = atomicAdd(&cur[eidx[N_EDGES + e]], 1);
        csr_src[pos] = eidx[e];
        int r  = eattr[2 * e];
        int cc = min(max(eattr[2 * e + 1], 0), MAX_CHILD - 1);
        csr_cid[pos] = r * MAX_CHILD + cc;
    }
}

// ---------------------------------------------------------------------------
// Edge aggregation (round-6 measured-good form): one warp per dst node, unroll-2.
// ---------------------------------------------------------------------------
__global__ void __launch_bounds__(256) edge_csr_kernel(
    const int*    __restrict__ off,
    const int*    __restrict__ deg,
    const int*    __restrict__ csr_src,
    const int*    __restrict__ csr_cid,
    const __half* __restrict__ combo,
    const __half* __restrict__ h,
    __half*       __restrict__ z)
{
    int n = blockIdx.x * 8 + (threadIdx.x >> 5);
    if (n >= N_NODES) return;
    int lane = threadIdx.x & 31;

    float4 hv = __ldg((const float4*)(h + (size_t)n * HIDDEN) + lane);
    __half2* hp = (__half2*)&hv;
    float2 a0 = __half22float2(hp[0]), a1 = __half22float2(hp[1]);
    float2 a2 = __half22float2(hp[2]), a3 = __half22float2(hp[3]);
    float acc[8] = {a0.x, a0.y, a1.x, a1.y, a2.x, a2.y, a3.x, a3.y};

    int start = off[n];
    int d = deg[n];
    int k = 0;

    for (; k + 2 <= d; k += 2) {
        int s0 = __ldg(&csr_src[start + k]);
        int c0 = __ldg(&csr_cid[start + k]);
        int s1 = __ldg(&csr_src[start + k + 1]);
        int c1 = __ldg(&csr_cid[start + k + 1]);

        float4 sv0 = __ldg((const float4*)(h + (size_t)s0 * HIDDEN) + lane);
        float4 cv0 = __ldg((const float4*)(combo + (size_t)c0 * HIDDEN) + lane);
        float4 sv1 = __ldg((const float4*)(h + (size_t)s1 * HIDDEN) + lane);
        float4 cv1 = __ldg((const float4*)(combo + (size_t)c1 * HIDDEN) + lane);

        __half2* sp0 = (__half2*)&sv0; __half2* cp0 = (__half2*)&cv0;
        __half2* sp1 = (__half2*)&sv1; __half2* cp1 = (__half2*)&cv1;
        #pragma unroll
        for (int j = 0; j < 4; j++) {
            float2 f0 = __half22float2(sp0[j]);
            float2 g0 = __half22float2(cp0[j]);
            float2 f1 = __half22float2(sp1[j]);
            float2 g1 = __half22float2(cp1[j]);
            acc[2 * j + 0] += fmaxf(f0.x + g0.x, 0.f) + fmaxf(f1.x + g1.x, 0.f);
            acc[2 * j + 1] += fmaxf(f0.y + g0.y, 0.f) + fmaxf(f1.y + g1.y, 0.f);
        }
    }
    if (k < d) {
        int s0 = __ldg(&csr_src[start + k]);
        int c0 = __ldg(&csr_cid[start + k]);
        float4 sv0 = __ldg((const float4*)(h + (size_t)s0 * HIDDEN) + lane);
        float4 cv0 = __ldg((const float4*)(combo + (size_t)c0 * HIDDEN) + lane);
        __half2* sp0 = (__half2*)&sv0; __half2* cp0 = (__half2*)&cv0;
        #pragma unroll
        for (int j = 0; j < 4; j++) {
            float2 f0 = __half22float2(sp0[j]);
            float2 g0 = __half22float2(cp0[j]);
            acc[2 * j + 0] += fmaxf(f0.x + g0.x, 0.f);
            acc[2 * j + 1] += fmaxf(f0.y + g0.y, 0.f);
        }
    }

    float4 outv;
    __half2* op = (__half2*)&outv;
    op[0] = __floats2half2_rn(acc[0], acc[1]);
    op[1] = __floats2half2_rn(acc[2], acc[3]);
    op[2] = __floats2half2_rn(acc[4], acc[5]);
    op[3] = __floats2half2_rn(acc[6], acc[7]);
    ((float4*)(z + (size_t)n * HIDDEN))[lane] = outv;
}

// ---------------------------------------------------------------------------
// Embed GEMM: BM=64, BN=256, BK=64, 256 threads, 2 CTAs/SM.
// Strength-reduced loaders: running global pointers + constant chunk offsets,
// hoisted validity predicates, precomputed smem indices.
// ---------------------------------------------------------------------------
__global__ void __launch_bounds__(256, 2) embed_gemm(
    const float* __restrict__ A, const __half* __restrict__ B,
    const float* __restrict__ bias,
    const int*   __restrict__ xidx,
    const float* __restrict__ label_emb,
    const float* __restrict__ type_emb,
    __half* __restrict__ h_out, int M)
{
    extern __shared__ __half smem[];
    __half* sA = smem;                 // 2 x EBM x ESA_STRIDE
    __half* sB = smem + ESA_ELEMS;     // 2 x EBK x SB_STRIDE

    const int tid  = threadIdx.x;
    const int lane = tid & 31;
    const int warp = tid >> 5;
    const int wm   = warp >> 2;        // 0..1
    const int wn   = warp & 3;         // 0..3
    const int mBase = blockIdx.x * EBM;

    // ---- loop-invariant loader decomposition ----
    const int a_row0 = tid >> 4;            // 0..15 ; chunk i adds 16*i
    const int a_col  = (tid & 15) << 2;     // float col 0..60
    const int b_row0 = tid >> 5;            // 0..7  ; chunk i adds 8*i
    const int b_col  = (tid & 31) << 3;     // half col 0..248

    const float*  aptr = A + (size_t)(mBase + a_row0) * SEM_IN + a_col;
    const __half* bptr = B + (size_t)b_row0 * HIDDEN + b_col;

    bool avalid[4];
    #pragma unroll
    for (int i = 0; i < 4; i++) avalid[i] = (mBase + a_row0 + 16 * i) < M;

    const int sA_idx = a_row0 * ESA_STRIDE + a_col;        // halves
    const uint32_t sB_addr0 = (uint32_t)__cvta_generic_to_shared(sB)
                            + (uint32_t)(b_row0 * SB_STRIDE + b_col) * 2;

    // fragment bases (per-warp, loop-invariant)
    const __half* aF0 = sA + (wm * 32 + (lane & 15)) * ESA_STRIDE + (lane >> 4) * 8;
    const __half* bF0 = sB + ((lane & 7) + ((lane >> 3) & 1) * 8) * SB_STRIDE
                           + wn * 64 + (lane >> 4) * 8;

    float4 ra[4];
    float acc[2][8][4];
    #pragma unroll
    for (int i = 0; i < 2; i++)
        #pragma unroll
        for (int j = 0; j < 8; j++)
            #pragma unroll
            for (int q = 0; q < 4; q++) acc[i][j][q] = 0.f;

    auto ldgA = [&]() {
        #pragma unroll
        for (int i = 0; i < 4; i++)
            ra[i] = avalid[i] ? *(const float4*)(aptr + i * (16 * SEM_IN))
                              : make_float4(0.f, 0.f, 0.f, 0.f);
        aptr += EBK;
    };
    auto stsA = [&](int st) {
        __half* base = sA + st * (EBM * ESA_STRIDE) + sA_idx;
        #pragma unroll
        for (int i = 0; i < 4; i++) {
            __half2* p = (__half2*)(base + i * (16 * ESA_STRIDE));
            p[0] = __floats2half2_rn(ra[i].x, ra[i].y);
            p[1] = __floats2half2_rn(ra[i].z, ra[i].w);
        }
    };
    auto cpB = [&](int st) {
        uint32_t s = sB_addr0 + (uint32_t)st * (EBK * SB_STRIDE * 2);
        #pragma unroll
        for (int i = 0; i < 8; i++)
            cp16_raw(s + i * (8 * SB_STRIDE * 2), bptr + i * (8 * HIDDEN));
        bptr += EBK * HIDDEN;
        CP_COMMIT();
    };

    ldgA(); cpB(0);
    stsA(0); CP_WAIT(0); __syncthreads();

    for (int kt = 0; kt < EKT; kt++) {
        const int st = kt & 1;
        if (kt + 1 < EKT) { ldgA(); cpB(st ^ 1); }
        const __half* aFst = aF0 + st * (EBM * ESA_STRIDE);
        const __half* bFst = bF0 + st * (EBK * SB_STRIDE);
        #pragma unroll
        for (int ks = 0; ks < 4; ks++) {
            uint32_t af[2][4], bf[4][4];
            #pragma unroll
            for (int mi = 0; mi < 2; mi++)
                ldsm_x4(af[mi], aFst + mi * (16 * ESA_STRIDE) + ks * 16);
            #pragma unroll
            for (int p2 = 0; p2 < 4; p2++)
                ldsm_x4t(bf[p2], bFst + ks * (16 * SB_STRIDE) + p2 * 16);
            #pragma unroll
            for (int mi = 0; mi < 2; mi++)
                #pragma unroll
                for (int ni = 0; ni < 8; ni++)
                    mma16816(acc[mi][ni], af[mi],
                             bf[ni >> 1][(ni & 1) * 2 + 0], bf[ni >> 1][(ni & 1) * 2 + 1]);
        }
        if (kt + 1 < EKT) { stsA(st ^ 1); CP_WAIT(0); }
        __syncthreads();
    }

    #pragma unroll
    for (int mi = 0; mi < 2; mi++) {
        int r0 = mBase + wm * 32 + mi * 16 + (lane >> 2);
        #pragma unroll
        for (int hh = 0; hh < 2; hh++) {
            int r = r0 + hh * 8;
            if (r >= M) continue;
            int x0 = xidx[2 * r], x1 = xidx[2 * r + 1];
            #pragma unroll
            for (int ni = 0; ni < 8; ni++) {
                int c = wn * 64 + ni * 8 + (lane & 3) * 2;
                float v0 = acc[mi][ni][hh * 2 + 0] + bias[c]
                         + label_emb[(size_t)x0 * HIDDEN + c] + type_emb[x1 * HIDDEN + c];
                float v1 = acc[mi][ni][hh * 2 + 1] + bias[c + 1]
                         + label_emb[(size_t)x0 * HIDDEN + c + 1] + type_emb[x1 * HIDDEN + c + 1];
                *(__half2*)(h_out + (size_t)r * HIDDEN + c) = __floats2half2_rn(v0, v1);
            }
        }
    }
}

// ---------------------------------------------------------------------------
// Fused MLP: BM=64, BN=256, BK=32, 256 threads, 2 CTAs/SM. (round-10 passing)
// ---------------------------------------------------------------------------
__global__ void __launch_bounds__(256, 2) fused_mlp(
    const __half* __restrict__ Z,
    const __half* __restrict__ W1, const float* __restrict__ b1,
    const __half* __restrict__ W2, const float* __restrict__ b2,
    __half* __restrict__ h_out, int M)
{
    extern __shared__ __half hsm[];
    __half* sT = hsm;                          // MBM x ST_STRIDE
    __half* sA = hsm + MST_ELEMS;              // 2 x MBM x MSA_STRIDE
    __half* sB = hsm + MST_ELEMS + MSA_ELEMS;  // 2 x BK x SB_STRIDE

    const int tid  = threadIdx.x;
    const int lane = tid & 31;
    const int warp = tid >> 5;
    const int wm   = warp >> 2;        // 0..1
    const int wn   = warp & 3;         // 0..3
    const int mBase = blockIdx.x * MBM;

    const int KT = HIDDEN / BK;        // 8

    float acc[2][8][4];
    #pragma unroll
    for (int i = 0; i < 2; i++)
        #pragma unroll
        for (int j = 0; j < 8; j++)
            #pragma unroll
            for (int q = 0; q < 4; q++) acc[i][j][q] = 0.f;

    auto cpA = [&](int kt, int st) {
        // 64 rows x 4 chunks(16B) = 256 chunks; all 256 threads
        int row = tid >> 2;
        int ch  = tid & 3;
        cp16(&sA[st * MBM * MSA_STRIDE + row * MSA_STRIDE + ch * 8],
             Z + (size_t)(mBase + row) * HIDDEN + kt * BK + ch * 8);
    };
    auto cpB = [&](const __half* W, int kt, int st) {
        #pragma unroll
        for (int i = 0; i < 4; i++) {
            int idx = tid + i * 256;
            int row = idx >> 5;
            int ch  = idx & 31;
            cp16(&sB[st * BK * SB_STRIDE + row * SB_STRIDE + ch * 8],
                 W + (size_t)(kt * BK + row) * HIDDEN + ch * 8);
        }
    };
    auto compute = [&](const __half* aBase, int aStride, int aColOff, int st) {
        #pragma unroll
        for (int ks = 0; ks < 2; ks++) {
            uint32_t af[2][4], bf[4][4];
            #pragma unroll
            for (int mi = 0; mi < 2; mi++)
                ldsm_x4(af[mi], aBase
                         + (wm * 32 + mi * 16 + (lane & 15)) * aStride
                         + aColOff + ks * 16 + (lane >> 4) * 8);
            #pragma unroll
            for (int p2 = 0; p2 < 4; p2++) {
                int krow = ks * 16 + (lane & 7) + ((lane >> 3) & 1) * 8;
                int ncol = wn * 64 + p2 * 16 + (lane >> 4) * 8;
                ldsm_x4t(bf[p2], &sB[st * BK * SB_STRIDE + krow * SB_STRIDE + ncol]);
            }
            #pragma unroll
            for (int mi = 0; mi < 2; mi++)
                #pragma unroll
                for (int ni = 0; ni < 8; ni++)
                    mma16816(acc[mi][ni], af[mi],
                             bf[ni >> 1][(ni & 1) * 2 + 0], bf[ni >> 1][(ni & 1) * 2 + 1]);
        }
    };

    // ---- Stage 1: t = relu(Z @ W1 + b1) -> sT ----
    cpA(0, 0); cpB(W1, 0, 0); CP_COMMIT(); CP_WAIT(0); __syncthreads();
    for (int kt = 0; kt < KT; kt++) {
        const int st = kt & 1;
        if (kt + 1 < KT) { cpA(kt + 1, st ^ 1); cpB(W1, kt + 1, st ^ 1); CP_COMMIT(); }
        compute(&sA[st * MBM * MSA_STRIDE], MSA_STRIDE, 0, st);
        if (kt + 1 < KT) CP_WAIT(0);
        __syncthreads();
    }

    // epilogue 1: relu(+b1) -> sT, reset acc
    #pragma unroll
    for (int mi = 0; mi < 2; mi++) {
        int rl = wm * 32 + mi * 16 + (lane >> 2);
        #pragma unroll
        for (int hh = 0; hh < 2; hh++) {
            int rr = rl + hh * 8;
            #pragma unroll
            for (int ni = 0; ni < 8; ni++) {
                int c = wn * 64 + ni * 8 + (lane & 3) * 2;
                float v0 = fmaxf(acc[mi][ni][hh * 2 + 0] + b1[c], 0.f);
                float v1 = fmaxf(acc[mi][ni][hh * 2 + 1] + b1[c + 1], 0.f);
                *(__half2*)&sT[rr * ST_STRIDE + c] = __floats2half2_rn(v0, v1);
                acc[mi][ni][hh * 2 + 0] = 0.f;
                acc[mi][ni][hh * 2 + 1] = 0.f;
            }
        }
    }

    // ---- Stage 2: out = t @ W2 + b2 ----
    cpB(W2, 0, 0); CP_COMMIT(); CP_WAIT(0); __syncthreads();
    for (int kt = 0; kt < KT; kt++) {
        const int st = kt & 1;
        if (kt + 1 < KT) { cpB(W2, kt + 1, st ^ 1); CP_COMMIT(); }
        compute(sT, ST_STRIDE, kt * BK, st);
        if (kt + 1 < KT) CP_WAIT(0);
        __syncthreads();
    }

    #pragma unroll
    for (int mi = 0; mi < 2; mi++) {
        int r0 = mBase + wm * 32 + mi * 16 + (lane >> 2);
        #pragma unroll
        for (int hh = 0; hh < 2; hh++) {
            int r = r0 + hh * 8;
            if (r >= M) continue;
            #pragma unroll
            for (int ni = 0; ni < 8; ni++) {
                int c = wn * 64 + ni * 8 + (lane & 3) * 2;
                float v0 = acc[mi][ni][hh * 2 + 0] + b2[c];
                float v1 = acc[mi][ni][hh * 2 + 1] + b2[c + 1];
                *(__half2*)(h_out + (size_t)r * HIDDEN + c) = __floats2half2_rn(v0, v1);
            }
        }
    }
}

// ---------------------------------------------------------------------------
// Pool (4-way row-parallel) + projection
// ---------------------------------------------------------------------------
__global__ void __launch_bounds__(512) pool_kernel(
    const __half* __restrict__ h,
    const int*    __restrict__ batch,
    float*        __restrict__ pooled)
{
    __shared__ float2 sbuf[4][128];
    int g = blockIdx.x;
    int tid = threadIdx.x;
    int rs = tid >> 7, c2 = tid & 127;

    int lo = 0, hi = N_NODES;
    while (lo < hi) { int mid = (lo + hi) >> 1; if (batch[mid] < g) lo = mid + 1; else hi = mid; }
    int start = lo;
    hi = N_NODES;
    while (lo < hi) { int mid = (lo + hi) >> 1; if (batch[mid] < g + 1) lo = mid + 1; else hi = mid; }
    int end = lo;

    float2 acc = make_float2(0.f, 0.f);
    for (int r = start + rs; r < end; r += 4) {
        float2 f = __half22float2(__ldg((const __half2*)(h + (size_t)r * HIDDEN) + c2));
        acc.x += f.x; acc.y += f.y;
    }
    sbuf[rs][c2] = acc;
    __syncthreads();
    if (rs == 0) {
        float2 s = sbuf[0][c2];
        #pragma unroll
        for (int j = 1; j < 4; j++) { s.x += sbuf[j][c2].x; s.y += sbuf[j][c2].y; }
        float inv = 1.f / fmaxf((float)(end - start), 1.f);
        *(float2*)(pooled + g * HIDDEN + c2 * 2) = make_float2(s.x * inv, s.y * inv);
    }
}

__global__ void __launch_bounds__(HIDDEN) proj_kernel(
    const float* __restrict__ pooled,
    const float* __restrict__ W,
    const float* __restrict__ b,
    float*       __restrict__ out)
{
    int g = blockIdx.x;
    int t = threadIdx.x;
    float acc = b[t];
    #pragma unroll 8
    for (int k = 0; k < HIDDEN; k++)
        acc += pooled[g * HIDDEN + k] * W[k * HIDDEN + t];
    out[g * HIDDEN + t] = acc;
}

// ---------------------------------------------------------------------------
extern "C" void kernel_launch(void* const* d_in, const int* in_sizes, int n_in,
                              void* d_out, int out_size)
{
    const int*   x        = (const int*)  d_in[0];
    const float* x_sem    = (const float*)d_in[1];
    const int*   eattr    = (const int*)  d_in[2];
    const int*   eidx     = (const int*)  d_in[3];
    const int*   batch    = (const int*)  d_in[4];
    const float* label    = (const float*)d_in[5];
    const float* type_emb = (const float*)d_in[6];
    const float* sem_W    = (const float*)d_in[7];
    const float* sem_b    = (const float*)d_in[8];
    const float* role     = (const float*)d_in[9];
    const float* child    = (const float*)d_in[10];
    const float* W1_0     = (const float*)d_in[11];
    const float* b1_0     = (const float*)d_in[12];
    const float* W2_0     = (const float*)d_in[13];
    const float* b2_0     = (const float*)d_in[14];
    const float* W1_1     = (const float*)d_in[15];
    const float* b1_1     = (const float*)d_in[16];
    const float* W2_1     = (const float*)d_in[17];
    const float* b2_1     = (const float*)d_in[18];
    const float* proj_W   = (const float*)d_in[19];
    const float* proj_b   = (const float*)d_in[20];
    float* out = (float*)d_out;

    __half *hP, *zP, *wP, *comboP;
    float *pP;
    int *degP, *offP, *curP, *srcP, *cidP, *bsP;
    cudaGetSymbolAddress((void**)&hP, g_h);
    cudaGetSymbolAddress((void**)&zP, g_z);
    cudaGetSymbolAddress((void**)&wP, g_w16);
    cudaGetSymbolAddress((void**)&comboP, g_combo);
    cudaGetSymbolAddress((void**)&pP, g_pool);
    cudaGetSymbolAddress((void**)&degP, g_deg);
    cudaGetSymbolAddress((void**)&offP, g_off);
    cudaGetSymbolAddress((void**)&curP, g_cur);
    cudaGetSymbolAddress((void**)&srcP, g_csr_src);
    cudaGetSymbolAddress((void**)&cidP, g_csr_cid);
    cudaGetSymbolAddress((void**)&bsP, g_bsum);

    __half* w_sem = wP;
    __half* w1_0  = wP + W_SEM_ELEMS;
    __half* w2_0  = w1_0 + W_HH_ELEMS;
    __half* w1_1  = w2_0 + W_HH_ELEMS;
    __half* w2_1  = w1_1 + W_HH_ELEMS;

    const int embed_smem = (ESA_ELEMS + ESB_ELEMS) * (int)sizeof(__half);        // ~86 KB
    const int fused_smem = (MST_ELEMS + MSA_ELEMS + MSB_ELEMS) * (int)sizeof(__half); // ~78 KB
    cudaFuncSetAttribute(embed_gemm, cudaFuncAttributeMaxDynamicSharedMemorySize, embed_smem);
    cudaFuncSetAttribute(fused_mlp,  cudaFuncAttributeMaxDynamicSharedMemorySize, fused_smem);

    const int embed_blocks = (N_NODES + EBM - 1) / EBM;   // 1563
    const int mlp_blocks   = (N_NODES + MBM - 1) / MBM;   // 1563
    const int node_blocks  = (N_NODES + 7) / 8;

    // Launch order: embed_gemm is MY 4th launch -> profiled.
    cvt_all_kernel<<<(CVT_TOTAL / 4 + 255) / 256, 256>>>(
        sem_W, W1_0, W2_0, W1_1, W2_1, wP, degP);                       // 1
    combo_kernel<<<N_COMBO, 128>>>(role, child, comboP);                // 2
    count_kernel<<<(N_EDGES + 255) / 256, 256>>>(eidx, degP);           // 3
    embed_gemm<<<embed_blocks, 256, embed_smem>>>(                      // 4 (PROFILED)
        x_sem, w_sem, sem_b, x, label, type_emb, hP, N_NODES);

    // CSR (independent of embed result)
    scan1_kernel<<<NBLK, SCAN_B>>>(degP, offP, bsP);
    scan2_kernel<<<1, 128>>>(bsP);
    scan3_kernel<<<(N_NODES + 255) / 256, 256>>>(offP, bsP, curP);
    scatter_kernel<<<(N_EDGES + 255) / 256, 256>>>(eidx, eattr, curP, srcP, cidP);

    // GINE layer 0
    edge_csr_kernel<<<node_blocks, 256>>>(offP, degP, srcP, cidP, comboP, hP, zP);
    fused_mlp<<<mlp_blocks, 256, fused_smem>>>(zP, w1_0, b1_0, w2_0, b2_0, hP, N_NODES);

    // GINE layer 1
    edge_csr_kernel<<<node_blocks, 256>>>(offP, degP, srcP, cidP, comboP, hP, zP);
    fused_mlp<<<mlp_blocks, 256, fused_smem>>>(zP, w1_1, b1_1, w2_1, b2_1, hP, N_NODES);

    // pool + projection
    pool_kernel<<<NUM_GRAPHS, 512>>>(hP, batch, pP);
    proj_kernel<<<NUM_GRAPHS, HIDDEN>>>(pP, proj_W, proj_b, out);
}